// round 2
// baseline (speedup 1.0000x reference)
#include <cuda_runtime.h>
#include <cuda_fp16.h>
#include <cstdint>

#define T_STEPS 256
#define BATCH   64
#define XDIM    512
#define HDIM    2048
#define G4      8192          // 4*HDIM
#define NCTAS   128
#define THREADS 256
#define ASTRIDE 40            // 32 halfs + 8 pad (bank-conflict-free)

// ---------------- device scratch (static: no allocs allowed) ----------------
__device__ __align__(16) __half d_in16 [T_STEPS * BATCH * XDIM];   // 16 MB
__device__ __align__(16) __half d_wih16[G4 * XDIM];                // 8 MB
__device__ __align__(16) __half d_whh16[G4 * HDIM];                // 32 MB
__device__ __align__(16) float  d_bsum [G4];
__device__ __align__(16) float  d_xproj[(size_t)T_STEPS * BATCH * G4]; // 512 MB
__device__ __align__(16) __half d_h16  [BATCH * HDIM];
__device__ __align__(16) float  d_c    [BATCH * HDIM];
__device__ __align__(16) float  d_gates[BATCH * G4];               // 2 MB
__device__ unsigned d_bar;

// ---------------- helpers ----------------
__device__ __forceinline__ void mma16816(float* c,
    uint32_t a0, uint32_t a1, uint32_t a2, uint32_t a3,
    uint32_t b0, uint32_t b1)
{
    asm volatile(
        "mma.sync.aligned.m16n8k16.row.col.f32.f16.f16.f32 "
        "{%0,%1,%2,%3},{%4,%5,%6,%7},{%8,%9},{%0,%1,%2,%3};\n"
        : "+f"(c[0]), "+f"(c[1]), "+f"(c[2]), "+f"(c[3])
        : "r"(a0), "r"(a1), "r"(a2), "r"(a3), "r"(b0), "r"(b1));
}

__device__ __forceinline__ float sigmoidf_fast(float x) {
    return 1.0f / (1.0f + __expf(-x));
}
__device__ __forceinline__ float tanhf_fast(float x) {
    // 1 - 2/(e^{2x}+1): stable at both extremes (inf -> 1, 0 -> -1)
    float e = __expf(2.0f * x);
    return 1.0f - 2.0f / (e + 1.0f);
}

// ---------------- phase 0: conversions / init ----------------
__global__ __launch_bounds__(256) void prep_kernel(
    const float* __restrict__ input, const float* __restrict__ h0,
    const float* __restrict__ c0,    const float* __restrict__ wih,
    const float* __restrict__ whh,   const float* __restrict__ bih,
    const float* __restrict__ bhh)
{
    const int i0 = blockIdx.x * blockDim.x + threadIdx.x;
    const int stride = gridDim.x * blockDim.x;
    if (i0 == 0) d_bar = 0u;
    for (int i = i0; i < T_STEPS * BATCH * XDIM; i += stride)
        d_in16[i] = __float2half(input[i]);
    for (int i = i0; i < G4 * XDIM; i += stride)
        d_wih16[i] = __float2half(wih[i]);
    for (int i = i0; i < G4 * HDIM; i += stride)
        d_whh16[i] = __float2half(whh[i]);
    for (int i = i0; i < G4; i += stride)
        d_bsum[i] = bih[i] + bhh[i];
    for (int i = i0; i < BATCH * HDIM; i += stride) {
        d_h16[i] = __float2half(h0[i]);
        d_c[i]   = c0[i];
    }
}

// ---------------- phase 1: x_proj = input @ w_ih^T + (b_ih + b_hh) ----------------
__global__ __launch_bounds__(THREADS) void xproj_kernel()
{
    __shared__ __align__(16) __half As[2][64 * ASTRIDE];
    __shared__ __align__(16) __half Bs[2][64 * ASTRIDE];

    const int tid  = threadIdx.x;
    const int lane = tid & 31, wid = tid >> 5;
    const int wm = wid >> 1, wn = wid & 1;       // 4 m-warps x 2 n-warps
    const int g  = lane >> 2, tq = lane & 3;
    const int n0 = blockIdx.x * 64;
    const int m0 = blockIdx.y * 64;
    const int lrow = tid >> 2, lc = (tid & 3) * 8;

    const __half* Ag = d_in16  + (m0 + lrow) * XDIM + lc;
    const __half* Bg = d_wih16 + (n0 + lrow) * XDIM + lc;

    float acc[4][4];
    #pragma unroll
    for (int i = 0; i < 4; i++)
        #pragma unroll
        for (int j = 0; j < 4; j++) acc[i][j] = 0.0f;

    uint4 ra = *(const uint4*)Ag;
    uint4 rb = *(const uint4*)Bg;
    *(uint4*)&As[0][lrow * ASTRIDE + lc] = ra;
    *(uint4*)&Bs[0][lrow * ASTRIDE + lc] = rb;
    __syncthreads();

    const int NIT = XDIM / 32;
    #pragma unroll 1
    for (int it = 0; it < NIT; ++it) {
        const int cur = it & 1;
        if (it + 1 < NIT) {
            ra = *(const uint4*)(Ag + (it + 1) * 32);
            rb = *(const uint4*)(Bg + (it + 1) * 32);
        }
        #pragma unroll
        for (int ks = 0; ks < 32; ks += 16) {
            const __half* ab = &As[cur][(wm * 16 + g) * ASTRIDE + ks + tq * 2];
            uint32_t a0 = *(const uint32_t*)(ab);
            uint32_t a1 = *(const uint32_t*)(ab + 8 * ASTRIDE);
            uint32_t a2 = *(const uint32_t*)(ab + 8);
            uint32_t a3 = *(const uint32_t*)(ab + 8 * ASTRIDE + 8);
            #pragma unroll
            for (int nf = 0; nf < 4; nf++) {
                const __half* bb = &Bs[cur][(wn * 32 + nf * 8 + g) * ASTRIDE + ks + tq * 2];
                uint32_t b0 = *(const uint32_t*)(bb);
                uint32_t b1 = *(const uint32_t*)(bb + 8);
                mma16816(acc[nf], a0, a1, a2, a3, b0, b1);
            }
        }
        if (it + 1 < NIT) {
            *(uint4*)&As[(it + 1) & 1][lrow * ASTRIDE + lc] = ra;
            *(uint4*)&Bs[(it + 1) & 1][lrow * ASTRIDE + lc] = rb;
        }
        __syncthreads();
    }

    #pragma unroll
    for (int nf = 0; nf < 4; nf++) {
        const int cb = n0 + wn * 32 + nf * 8 + tq * 2;
        const int r0 = m0 + wm * 16 + g;
        float2 bsv = *(const float2*)(d_bsum + cb);
        float2 v0 = make_float2(acc[nf][0] + bsv.x, acc[nf][1] + bsv.y);
        float2 v1 = make_float2(acc[nf][2] + bsv.x, acc[nf][3] + bsv.y);
        *(float2*)(d_xproj + (size_t)r0 * G4 + cb)       = v0;
        *(float2*)(d_xproj + (size_t)(r0 + 8) * G4 + cb) = v1;
    }
}

// ---------------- grid barrier (all 128 CTAs co-resident: grid <= #SMs) ----------------
__device__ __forceinline__ void grid_barrier(unsigned target)
{
    __syncthreads();
    if (threadIdx.x == 0) {
        __threadfence();
        atomicAdd(&d_bar, 1u);
        volatile unsigned* p = &d_bar;
        while (*p < target) { }
        __threadfence();
    }
    __syncthreads();
}

// ---------------- phase 2: persistent recurrent kernel ----------------
__global__ __launch_bounds__(THREADS) void lstm_persistent(float* __restrict__ out)
{
    __shared__ __align__(16) __half As[2][64 * ASTRIDE];
    __shared__ __align__(16) __half Bs[2][64 * ASTRIDE];
    __shared__ float rs[34];

    const int cta  = blockIdx.x;
    const int tid  = threadIdx.x;
    const int lane = tid & 31, wid = tid >> 5;
    const int wm = wid >> 1, wn = wid & 1;
    const int g  = lane >> 2, tq = lane & 3;
    const int n0 = cta * 64;
    const int lrow = tid >> 2, lc = (tid & 3) * 8;

    const __half* Ag = d_h16   + lrow * HDIM + lc;                  // h rows = batch
    const __half* Bg = d_whh16 + (size_t)(n0 + lrow) * HDIM + lc;   // weight slice

    const size_t HOFF = (size_t)T_STEPS * BATCH * HDIM;
    const size_t COFF = HOFF + (size_t)BATCH * HDIM;

    unsigned bar_target = 0;
    const int NIT = HDIM / 32;

    for (int t = 0; t < T_STEPS; ++t) {
        // ---------- GEMM: gates[b, n0..n0+63] = h16 @ w_hh^T + x_proj[t] ----------
        float acc[4][4];
        #pragma unroll
        for (int i = 0; i < 4; i++)
            #pragma unroll
            for (int j = 0; j < 4; j++) acc[i][j] = 0.0f;

        uint4 ra = *(const uint4*)Ag;
        uint4 rb = *(const uint4*)Bg;
        *(uint4*)&As[0][lrow * ASTRIDE + lc] = ra;
        *(uint4*)&Bs[0][lrow * ASTRIDE + lc] = rb;
        __syncthreads();

        #pragma unroll 1
        for (int it = 0; it < NIT; ++it) {
            const int cur = it & 1;
            if (it + 1 < NIT) {
                ra = *(const uint4*)(Ag + (it + 1) * 32);
                rb = *(const uint4*)(Bg + (it + 1) * 32);
            }
            #pragma unroll
            for (int ks = 0; ks < 32; ks += 16) {
                const __half* ab = &As[cur][(wm * 16 + g) * ASTRIDE + ks + tq * 2];
                uint32_t a0 = *(const uint32_t*)(ab);
                uint32_t a1 = *(const uint32_t*)(ab + 8 * ASTRIDE);
                uint32_t a2 = *(const uint32_t*)(ab + 8);
                uint32_t a3 = *(const uint32_t*)(ab + 8 * ASTRIDE + 8);
                #pragma unroll
                for (int nf = 0; nf < 4; nf++) {
                    const __half* bb = &Bs[cur][(wn * 32 + nf * 8 + g) * ASTRIDE + ks + tq * 2];
                    uint32_t b0 = *(const uint32_t*)(bb);
                    uint32_t b1 = *(const uint32_t*)(bb + 8);
                    mma16816(acc[nf], a0, a1, a2, a3, b0, b1);
                }
            }
            if (it + 1 < NIT) {
                *(uint4*)&As[(it + 1) & 1][lrow * ASTRIDE + lc] = ra;
                *(uint4*)&Bs[(it + 1) & 1][lrow * ASTRIDE + lc] = rb;
            }
            __syncthreads();
        }

        // epilogue: += x_proj, write gates
        {
            const float* xp = d_xproj + (size_t)t * BATCH * G4;
            #pragma unroll
            for (int nf = 0; nf < 4; nf++) {
                const int cb = n0 + wn * 32 + nf * 8 + tq * 2;
                const int r0 = wm * 16 + g;
                float2 x0 = *(const float2*)(xp + (size_t)r0 * G4 + cb);
                float2 x1 = *(const float2*)(xp + (size_t)(r0 + 8) * G4 + cb);
                float2 v0 = make_float2(acc[nf][0] + x0.x, acc[nf][1] + x0.y);
                float2 v1 = make_float2(acc[nf][2] + x1.x, acc[nf][3] + x1.y);
                *(float2*)(d_gates + (size_t)r0 * G4 + cb)       = v0;
                *(float2*)(d_gates + (size_t)(r0 + 8) * G4 + cb) = v1;
            }
        }

        bar_target += NCTAS;
        grid_barrier(bar_target);

        // ---------- pointwise + softmax: CTAs 0..63, one batch row each ----------
        if (cta < BATCH) {
            const int b = cta;
            const float* gb = d_gates + (size_t)b * G4;
            float*       cb = d_c     + b * HDIM;

            float hv[HDIM / THREADS];   // 8
            float lmax = -1e30f;
            #pragma unroll
            for (int k = 0; k < HDIM / THREADS; ++k) {
                const int j = tid + k * THREADS;
                float ip = gb[j];
                float fp = gb[HDIM + j];
                float gp = gb[2 * HDIM + j];
                float op = gb[3 * HDIM + j];
                float ii = sigmoidf_fast(ip);
                float ff = sigmoidf_fast(fp);
                float gg = tanhf_fast(gp);
                float oo = sigmoidf_fast(op);
                float cn = ff * cb[j] + ii * gg;
                cb[j] = cn;
                float hn = oo * tanhf_fast(cn);
                d_h16[b * HDIM + j] = __float2half(hn);
                if (t == T_STEPS - 1) {
                    out[HOFF + (size_t)b * HDIM + j] = hn;
                    out[COFF + (size_t)b * HDIM + j] = cn;
                }
                hv[k] = hn;
                lmax = fmaxf(lmax, hn);
            }
            // block max
            float v = lmax;
            #pragma unroll
            for (int o = 16; o > 0; o >>= 1) v = fmaxf(v, __shfl_xor_sync(0xffffffffu, v, o));
            if (lane == 0) rs[wid] = v;
            __syncthreads();
            if (tid == 0) {
                float m = rs[0];
                #pragma unroll
                for (int i = 1; i < THREADS / 32; i++) m = fmaxf(m, rs[i]);
                rs[32] = m;
            }
            __syncthreads();
            const float M = rs[32];
            // exp + block sum
            float lsum = 0.0f;
            #pragma unroll
            for (int k = 0; k < HDIM / THREADS; ++k) {
                float e = __expf(hv[k] - M);
                hv[k] = e;
                lsum += e;
            }
            v = lsum;
            #pragma unroll
            for (int o = 16; o > 0; o >>= 1) v += __shfl_xor_sync(0xffffffffu, v, o);
            if (lane == 0) rs[wid] = v;
            __syncthreads();
            if (tid == 0) {
                float s = 0.0f;
                #pragma unroll
                for (int i = 0; i < THREADS / 32; i++) s += rs[i];
                rs[33] = s;
            }
            __syncthreads();
            const float inv = 1.0f / rs[33];
            float* yrow = out + (size_t)t * BATCH * HDIM + (size_t)b * HDIM;
            #pragma unroll
            for (int k = 0; k < HDIM / THREADS; ++k) {
                const int j = tid + k * THREADS;
                yrow[j] = hv[k] * inv;
            }
        }

        bar_target += NCTAS;
        grid_barrier(bar_target);
    }
}

// ---------------- entry ----------------
extern "C" void kernel_launch(void* const* d_in, const int* in_sizes, int n_in,
                              void* d_out, int out_size)
{
    (void)in_sizes; (void)n_in; (void)out_size;
    const float* input = (const float*)d_in[0];
    const float* h0    = (const float*)d_in[1];
    const float* c0    = (const float*)d_in[2];
    const float* wih   = (const float*)d_in[3];
    const float* whh   = (const float*)d_in[4];
    const float* bih   = (const float*)d_in[5];
    const float* bhh   = (const float*)d_in[6];

    prep_kernel<<<1024, 256>>>(input, h0, c0, wih, whh, bih, bhh);
    xproj_kernel<<<dim3(G4 / 64, (T_STEPS * BATCH) / 64), THREADS>>>();
    lstm_persistent<<<NCTAS, THREADS>>>((float*)d_out);
}

// round 3
// speedup vs baseline: 1.6667x; 1.6667x over previous
#include <cuda_runtime.h>
#include <cuda_fp16.h>
#include <cstdint>

#define T_STEPS 256
#define BATCH   64
#define XDIM    512
#define HDIM    2048
#define G4      8192          // 4*HDIM
#define NCTAS   128
#define PTHREADS 512          // persistent kernel threads
#define XTHREADS 256          // xproj kernel threads
#define ASTRIDE 40            // 32 halfs + 8 pad (bank-conflict-free)
#define GSTR    68            // gate smem row stride (floats)
#define TILEH   (64*ASTRIDE)  // halfs per 64x32 tile

// ---------------- device scratch (static: no allocs allowed) ----------------
__device__ __align__(16) __half d_in16 [T_STEPS * BATCH * XDIM];       // 16 MB
__device__ __align__(16) __half d_wih16[G4 * XDIM];                    // 8 MB  (permuted rows)
__device__ __align__(16) __half d_whh16[G4 * HDIM];                    // 32 MB (permuted rows)
__device__ __align__(16) float  d_bsum [G4];                           // permuted
__device__ __align__(16) float  d_xproj[(size_t)T_STEPS * BATCH * G4]; // 512 MB (permuted cols)
__device__ __align__(16) __half d_h16  [2][BATCH * HDIM];              // double-buffered
__device__ __align__(16) float  d_sum  [T_STEPS * BATCH];              // softmax denominators
__device__ unsigned d_bar;

// ---------------- helpers ----------------
__device__ __forceinline__ void mma16816(float* c,
    uint32_t a0, uint32_t a1, uint32_t a2, uint32_t a3,
    uint32_t b0, uint32_t b1)
{
    asm volatile(
        "mma.sync.aligned.m16n8k16.row.col.f32.f16.f16.f32 "
        "{%0,%1,%2,%3},{%4,%5,%6,%7},{%8,%9},{%0,%1,%2,%3};\n"
        : "+f"(c[0]), "+f"(c[1]), "+f"(c[2]), "+f"(c[3])
        : "r"(a0), "r"(a1), "r"(a2), "r"(a3), "r"(b0), "r"(b1));
}

__device__ __forceinline__ float sigmoidf_fast(float x) {
    return 1.0f / (1.0f + __expf(-x));
}
__device__ __forceinline__ float tanhf_fast(float x) {
    float e = __expf(2.0f * x);
    return 1.0f - 2.0f / (e + 1.0f);
}

__device__ __forceinline__ uint32_t smem_u32(const void* p) {
    return (uint32_t)__cvta_generic_to_shared(p);
}
#define CP16(dst_u32, src_ptr) \
    asm volatile("cp.async.cg.shared.global [%0], [%1], 16;\n" :: "r"(dst_u32), "l"(src_ptr))
#define CP_COMMIT() asm volatile("cp.async.commit_group;\n" ::: "memory")
#define CP_WAIT1()  asm volatile("cp.async.wait_group 1;\n" ::: "memory")

// row permutation: dst row r (CTA-major, gate-interleaved) -> src gate row
__device__ __forceinline__ int perm_src_row(int r) {
    int cta = r >> 6;
    int ln  = r & 63;
    int gate = ln >> 4;
    int jj   = ln & 15;
    return gate * HDIM + cta * 16 + jj;
}

// ---------------- phase 0: conversions / init / permutation ----------------
__global__ __launch_bounds__(256) void prep_kernel(
    const float* __restrict__ input, const float* __restrict__ h0,
    const float* __restrict__ c0,    const float* __restrict__ wih,
    const float* __restrict__ whh,   const float* __restrict__ bih,
    const float* __restrict__ bhh)
{
    (void)c0;
    const int i0 = blockIdx.x * blockDim.x + threadIdx.x;
    const int stride = gridDim.x * blockDim.x;
    if (i0 == 0) d_bar = 0u;
    for (int i = i0; i < T_STEPS * BATCH * XDIM; i += stride)
        d_in16[i] = __float2half(input[i]);
    for (int i = i0; i < G4 * XDIM; i += stride) {
        int r = i >> 9, k = i & (XDIM - 1);
        d_wih16[i] = __float2half(wih[perm_src_row(r) * XDIM + k]);
    }
    for (int i = i0; i < G4 * HDIM; i += stride) {
        int r = i >> 11, k = i & (HDIM - 1);
        d_whh16[i] = __float2half(whh[(size_t)perm_src_row(r) * HDIM + k]);
    }
    for (int i = i0; i < G4; i += stride) {
        int s = perm_src_row(i);
        d_bsum[i] = bih[s] + bhh[s];
    }
    for (int i = i0; i < BATCH * HDIM; i += stride)
        d_h16[0][i] = __float2half(h0[i]);
    for (int i = i0; i < T_STEPS * BATCH; i += stride)
        d_sum[i] = 0.0f;
}

// ---------------- phase 1: x_proj = input @ w_ih^T + (b_ih + b_hh), permuted cols ----------------
__global__ __launch_bounds__(XTHREADS) void xproj_kernel()
{
    __shared__ __align__(16) __half As[2][64 * ASTRIDE];
    __shared__ __align__(16) __half Bs[2][64 * ASTRIDE];

    const int tid  = threadIdx.x;
    const int lane = tid & 31, wid = tid >> 5;
    const int wm = wid >> 1, wn = wid & 1;       // 4 m-warps x 2 n-warps
    const int gq = lane >> 2, tq = lane & 3;
    const int n0 = blockIdx.x * 64;
    const int m0 = blockIdx.y * 64;
    const int lrow = tid >> 2, lc = (tid & 3) * 8;

    const __half* Ag = d_in16  + (m0 + lrow) * XDIM + lc;
    const __half* Bg = d_wih16 + (n0 + lrow) * XDIM + lc;

    float acc[4][4];
    #pragma unroll
    for (int i = 0; i < 4; i++)
        #pragma unroll
        for (int j = 0; j < 4; j++) acc[i][j] = 0.0f;

    uint4 ra = *(const uint4*)Ag;
    uint4 rb = *(const uint4*)Bg;
    *(uint4*)&As[0][lrow * ASTRIDE + lc] = ra;
    *(uint4*)&Bs[0][lrow * ASTRIDE + lc] = rb;
    __syncthreads();

    const int NIT = XDIM / 32;
    #pragma unroll 1
    for (int it = 0; it < NIT; ++it) {
        const int cur = it & 1;
        if (it + 1 < NIT) {
            ra = *(const uint4*)(Ag + (it + 1) * 32);
            rb = *(const uint4*)(Bg + (it + 1) * 32);
        }
        #pragma unroll
        for (int ks = 0; ks < 32; ks += 16) {
            const __half* ab = &As[cur][(wm * 16 + gq) * ASTRIDE + ks + tq * 2];
            uint32_t a0 = *(const uint32_t*)(ab);
            uint32_t a1 = *(const uint32_t*)(ab + 8 * ASTRIDE);
            uint32_t a2 = *(const uint32_t*)(ab + 8);
            uint32_t a3 = *(const uint32_t*)(ab + 8 * ASTRIDE + 8);
            #pragma unroll
            for (int nf = 0; nf < 4; nf++) {
                const __half* bb = &Bs[cur][(wn * 32 + nf * 8 + gq) * ASTRIDE + ks + tq * 2];
                uint32_t b0 = *(const uint32_t*)(bb);
                uint32_t b1 = *(const uint32_t*)(bb + 8);
                mma16816(acc[nf], a0, a1, a2, a3, b0, b1);
            }
        }
        if (it + 1 < NIT) {
            *(uint4*)&As[(it + 1) & 1][lrow * ASTRIDE + lc] = ra;
            *(uint4*)&Bs[(it + 1) & 1][lrow * ASTRIDE + lc] = rb;
        }
        __syncthreads();
    }

    #pragma unroll
    for (int nf = 0; nf < 4; nf++) {
        const int cb = n0 + wn * 32 + nf * 8 + tq * 2;
        const int r0 = m0 + wm * 16 + gq;
        float2 bsv = *(const float2*)(d_bsum + cb);
        float2 v0 = make_float2(acc[nf][0] + bsv.x, acc[nf][1] + bsv.y);
        float2 v1 = make_float2(acc[nf][2] + bsv.x, acc[nf][3] + bsv.y);
        *(float2*)(d_xproj + (size_t)r0 * G4 + cb)       = v0;
        *(float2*)(d_xproj + (size_t)(r0 + 8) * G4 + cb) = v1;
    }
}

// ---------------- grid barrier (128 CTAs, all co-resident) ----------------
__device__ __forceinline__ void grid_barrier(unsigned target)
{
    __syncthreads();
    if (threadIdx.x == 0) {
        __threadfence();
        atomicAdd(&d_bar, 1u);
        volatile unsigned* p = &d_bar;
        while (*p < target) { }
        __threadfence();
    }
    __syncthreads();
}

// ---------------- phase 2: persistent recurrent kernel ----------------
__global__ __launch_bounds__(PTHREADS, 1) void lstm_persistent(float* __restrict__ out)
{
    extern __shared__ __align__(16) char smem_raw[];
    __half* sAll = (__half*)smem_raw;
    // [group][stage][64*ASTRIDE] for A and B; then gate sums [2][64][GSTR] floats
    float* gsum = (float*)(sAll + 12 * TILEH);

    const int cta  = blockIdx.x;
    const int tid  = threadIdx.x;
    const int lane = tid & 31;
    const int g    = tid >> 8;          // warp-group: K half
    const int gtid = tid & 255;
    const int gwid = gtid >> 5;
    const int wm = gwid >> 1, wn = gwid & 1;   // 4 m-warps x 2 n-warps per group
    const int gq = lane >> 2, tq = lane & 3;
    const int n0 = cta * 64;            // permuted gate-row base for this CTA
    const int lrow = gtid >> 2, lc = (gtid & 3) * 8;
    const int KOFF = g * (HDIM / 2);
    const int NIT  = (HDIM / 2) / 32;   // 32

    __half* sA = sAll + (size_t)g * 3 * TILEH;
    __half* sB = sAll + 6 * TILEH + (size_t)g * 3 * TILEH;

    const size_t HOFF = (size_t)T_STEPS * BATCH * HDIM;
    const size_t COFF = HOFF + (size_t)BATCH * HDIM;

    // persistent c state in registers: items tid and tid+512 of (b, jj) grid
    const int i1 = tid,        b1 = i1 >> 4, jj1 = i1 & 15;
    const int i2 = tid + 512,  b2 = i2 >> 4, jj2 = i2 & 15;
    float creg1, creg2;
    {
        // read initial c directly from input pointer passed via d_xproj? No:
        // c0 is passed through out? -> we stash c0 pointer via constant below.
    }
    // c0 comes in through a second kernel parameter instead:
    // (filled right after parameter list; see launch)
    // -- placeholder, real init below in code body --

    // NOTE: creg init moved below (needs c0 pointer param) — see kernel args.
    creg1 = 0.f; creg2 = 0.f; // overwritten

    unsigned bar_target = 0;

    // ---- initial c load (c0 passed as second param) ----
    // (handled via out2 param below)
    // --------------------------------------------------------------

    // actual parameters continue:
    // (see function signature extension)
    //

    // The code below is generated with c0 available:
    // placeholder removed in real signature version.

    for (int t = 0; t < T_STEPS; ++t) {
        const __half* hbuf = d_h16[t & 1];
        // -------- GEMM: this group's K half --------
        float acc[4][4];
        #pragma unroll
        for (int i = 0; i < 4; i++)
            #pragma unroll
            for (int j = 0; j < 4; j++) acc[i][j] = 0.0f;

        // prologue: stages 0,1
        #pragma unroll
        for (int st = 0; st < 2; ++st) {
            const int kb = KOFF + st * 32;
            CP16(smem_u32(sA + st * TILEH + lrow * ASTRIDE + lc),
                 hbuf + lrow * HDIM + kb + lc);
            CP16(smem_u32(sB + st * TILEH + lrow * ASTRIDE + lc),
                 d_whh16 + (size_t)(n0 + lrow) * HDIM + kb + lc);
            CP_COMMIT();
        }

        #pragma unroll 1
        for (int it = 0; it < NIT; ++it) {
            CP_WAIT1();
            asm volatile("bar.sync %0, 256;\n" :: "r"(g + 1) : "memory");
            const int cur = it % 3;
            const __half* At = sA + cur * TILEH;
            const __half* Bt = sB + cur * TILEH;
            #pragma unroll
            for (int ks = 0; ks < 32; ks += 16) {
                const __half* ab = At + (wm * 16 + gq) * ASTRIDE + ks + tq * 2;
                uint32_t a0 = *(const uint32_t*)(ab);
                uint32_t a1 = *(const uint32_t*)(ab + 8 * ASTRIDE);
                uint32_t a2 = *(const uint32_t*)(ab + 8);
                uint32_t a3 = *(const uint32_t*)(ab + 8 * ASTRIDE + 8);
                #pragma unroll
                for (int nf = 0; nf < 4; nf++) {
                    const __half* bb = Bt + (wn * 32 + nf * 8 + gq) * ASTRIDE + ks + tq * 2;
                    uint32_t b0 = *(const uint32_t*)(bb);
                    uint32_t b1 = *(const uint32_t*)(bb + 8);
                    mma16816(acc[nf], a0, a1, a2, a3, b0, b1);
                }
            }
            const int nxt = it + 2;
            if (nxt < NIT) {
                const int slot = nxt % 3;
                const int kb = KOFF + nxt * 32;
                CP16(smem_u32(sA + slot * TILEH + lrow * ASTRIDE + lc),
                     hbuf + lrow * HDIM + kb + lc);
                CP16(smem_u32(sB + slot * TILEH + lrow * ASTRIDE + lc),
                     d_whh16 + (size_t)(n0 + lrow) * HDIM + kb + lc);
            }
            CP_COMMIT();
        }

        // -------- epilogue: write group partials to SMEM --------
        #pragma unroll
        for (int nf = 0; nf < 4; nf++) {
            const int cb = wn * 32 + nf * 8 + tq * 2;
            const int r0 = wm * 16 + gq;
            *(float2*)&gsum[((size_t)g * 64 + r0) * GSTR + cb]     = make_float2(acc[nf][0], acc[nf][1]);
            *(float2*)&gsum[((size_t)g * 64 + r0 + 8) * GSTR + cb] = make_float2(acc[nf][2], acc[nf][3]);
        }
        __syncthreads();

        // -------- pointwise LSTM + exp + partial softmax sum --------
        __half* hN = d_h16[(t + 1) & 1];
        const float* xp = d_xproj + (size_t)t * BATCH * G4 + (size_t)0 * G4 + n0;
        float e1, e2;
        {
            const float* g0 = &gsum[(size_t)b1 * GSTR];
            const float* g1 = &gsum[(size_t)(64 + b1) * GSTR];
            const float* xr = xp + (size_t)b1 * G4;
            float ip = g0[jj1]      + g1[jj1]      + xr[jj1];
            float fp = g0[16 + jj1] + g1[16 + jj1] + xr[16 + jj1];
            float gp = g0[32 + jj1] + g1[32 + jj1] + xr[32 + jj1];
            float op = g0[48 + jj1] + g1[48 + jj1] + xr[48 + jj1];
            float ii = sigmoidf_fast(ip), ff = sigmoidf_fast(fp);
            float gg = tanhf_fast(gp),    oo = sigmoidf_fast(op);
            float cn = ff * creg1 + ii * gg;
            creg1 = cn;
            float hn = oo * tanhf_fast(cn);
            hN[b1 * HDIM + cta * 16 + jj1] = __float2half(hn);
            if (t == T_STEPS - 1) {
                out[HOFF + (size_t)b1 * HDIM + cta * 16 + jj1] = hn;
                out[COFF + (size_t)b1 * HDIM + cta * 16 + jj1] = cn;
            }
            e1 = __expf(hn);
        }
        {
            const float* g0 = &gsum[(size_t)b2 * GSTR];
            const float* g1 = &gsum[(size_t)(64 + b2) * GSTR];
            const float* xr = xp + (size_t)b2 * G4;
            float ip = g0[jj2]      + g1[jj2]      + xr[jj2];
            float fp = g0[16 + jj2] + g1[16 + jj2] + xr[16 + jj2];
            float gp = g0[32 + jj2] + g1[32 + jj2] + xr[32 + jj2];
            float op = g0[48 + jj2] + g1[48 + jj2] + xr[48 + jj2];
            float ii = sigmoidf_fast(ip), ff = sigmoidf_fast(fp);
            float gg = tanhf_fast(gp),    oo = sigmoidf_fast(op);
            float cn = ff * creg2 + ii * gg;
            creg2 = cn;
            float hn = oo * tanhf_fast(cn);
            hN[b2 * HDIM + cta * 16 + jj2] = __float2half(hn);
            if (t == T_STEPS - 1) {
                out[HOFF + (size_t)b2 * HDIM + cta * 16 + jj2] = hn;
                out[COFF + (size_t)b2 * HDIM + cta * 16 + jj2] = cn;
            }
            e2 = __expf(hn);
        }
        // 16-lane (same-b) reduction, then one red.add per b-group
        float v1 = e1, v2 = e2;
        #pragma unroll
        for (int o = 8; o > 0; o >>= 1) {
            v1 += __shfl_xor_sync(0xffffffffu, v1, o);
            v2 += __shfl_xor_sync(0xffffffffu, v2, o);
        }
        if ((lane & 15) == 0) {
            atomicAdd(&d_sum[t * BATCH + b1], v1);
            atomicAdd(&d_sum[t * BATCH + b2], v2);
        }

        bar_target += NCTAS;
        grid_barrier(bar_target);

        // -------- normalize & write y --------
        {
            float s1 = __ldcg(&d_sum[t * BATCH + b1]);
            float s2 = __ldcg(&d_sum[t * BATCH + b2]);
            out[(size_t)t * BATCH * HDIM + (size_t)b1 * HDIM + cta * 16 + jj1] = e1 * (1.0f / s1);
            out[(size_t)t * BATCH * HDIM + (size_t)b2 * HDIM + cta * 16 + jj2] = e2 * (1.0f / s2);
        }
    }
}

// second persistent-kernel param trick isn't needed if we read c0 in-kernel:
// we pass c0 pointer as a kernel argument via a small wrapper below.
__global__ __launch_bounds__(PTHREADS, 1) void lstm_persistent_c0(
    float* __restrict__ out, const float* __restrict__ c0);

// Real implementation with c0 parameter (the one above is unused).
__global__ __launch_bounds__(PTHREADS, 1) void lstm_persistent_c0(
    float* __restrict__ out, const float* __restrict__ c0)
{
    extern __shared__ __align__(16) char smem_raw[];
    __half* sAll = (__half*)smem_raw;
    float* gsum = (float*)(sAll + 12 * TILEH);

    const int cta  = blockIdx.x;
    const int tid  = threadIdx.x;
    const int lane = tid & 31;
    const int g    = tid >> 8;
    const int gtid = tid & 255;
    const int gwid = gtid >> 5;
    const int wm = gwid >> 1, wn = gwid & 1;
    const int gq = lane >> 2, tq = lane & 3;
    const int n0 = cta * 64;
    const int lrow = gtid >> 2, lc = (gtid & 3) * 8;
    const int KOFF = g * (HDIM / 2);
    const int NIT  = (HDIM / 2) / 32;

    __half* sA = sAll + (size_t)g * 3 * TILEH;
    __half* sB = sAll + 6 * TILEH + (size_t)g * 3 * TILEH;

    const size_t HOFF = (size_t)T_STEPS * BATCH * HDIM;
    const size_t COFF = HOFF + (size_t)BATCH * HDIM;

    const int i1 = tid,        b1 = i1 >> 4, jj1 = i1 & 15;
    const int i2 = tid + 512,  b2 = i2 >> 4, jj2 = i2 & 15;
    float creg1 = c0[b1 * HDIM + cta * 16 + jj1];
    float creg2 = c0[b2 * HDIM + cta * 16 + jj2];

    unsigned bar_target = 0;

    #pragma unroll 1
    for (int t = 0; t < T_STEPS; ++t) {
        const __half* hbuf = d_h16[t & 1];
        float acc[4][4];
        #pragma unroll
        for (int i = 0; i < 4; i++)
            #pragma unroll
            for (int j = 0; j < 4; j++) acc[i][j] = 0.0f;

        #pragma unroll
        for (int st = 0; st < 2; ++st) {
            const int kb = KOFF + st * 32;
            CP16(smem_u32(sA + st * TILEH + lrow * ASTRIDE + lc),
                 hbuf + lrow * HDIM + kb + lc);
            CP16(smem_u32(sB + st * TILEH + lrow * ASTRIDE + lc),
                 d_whh16 + (size_t)(n0 + lrow) * HDIM + kb + lc);
            CP_COMMIT();
        }

        #pragma unroll 1
        for (int it = 0; it < NIT; ++it) {
            CP_WAIT1();
            asm volatile("bar.sync %0, 256;\n" :: "r"(g + 1) : "memory");
            const int cur = it % 3;
            const __half* At = sA + cur * TILEH;
            const __half* Bt = sB + cur * TILEH;
            #pragma unroll
            for (int ks = 0; ks < 32; ks += 16) {
                const __half* ab = At + (wm * 16 + gq) * ASTRIDE + ks + tq * 2;
                uint32_t a0 = *(const uint32_t*)(ab);
                uint32_t a1 = *(const uint32_t*)(ab + 8 * ASTRIDE);
                uint32_t a2 = *(const uint32_t*)(ab + 8);
                uint32_t a3 = *(const uint32_t*)(ab + 8 * ASTRIDE + 8);
                #pragma unroll
                for (int nf = 0; nf < 4; nf++) {
                    const __half* bb = Bt + (wn * 32 + nf * 8 + gq) * ASTRIDE + ks + tq * 2;
                    uint32_t b0 = *(const uint32_t*)(bb);
                    uint32_t b1 = *(const uint32_t*)(bb + 8);
                    mma16816(acc[nf], a0, a1, a2, a3, b0, b1);
                }
            }
            const int nxt = it + 2;
            if (nxt < NIT) {
                const int slot = nxt % 3;
                const int kb = KOFF + nxt * 32;
                CP16(smem_u32(sA + slot * TILEH + lrow * ASTRIDE + lc),
                     hbuf + lrow * HDIM + kb + lc);
                CP16(smem_u32(sB + slot * TILEH + lrow * ASTRIDE + lc),
                     d_whh16 + (size_t)(n0 + lrow) * HDIM + kb + lc);
            }
            CP_COMMIT();
        }

        #pragma unroll
        for (int nf = 0; nf < 4; nf++) {
            const int cb = wn * 32 + nf * 8 + tq * 2;
            const int r0 = wm * 16 + gq;
            *(float2*)&gsum[((size_t)g * 64 + r0) * GSTR + cb]     = make_float2(acc[nf][0], acc[nf][1]);
            *(float2*)&gsum[((size_t)g * 64 + r0 + 8) * GSTR + cb] = make_float2(acc[nf][2], acc[nf][3]);
        }
        __syncthreads();

        __half* hN = d_h16[(t + 1) & 1];
        const float* xp = d_xproj + (size_t)t * BATCH * G4 + n0;
        float e1, e2;
        {
            const float* g0 = &gsum[(size_t)b1 * GSTR];
            const float* g1 = &gsum[(size_t)(64 + b1) * GSTR];
            const float* xr = xp + (size_t)b1 * G4;
            float ip = g0[jj1]      + g1[jj1]      + xr[jj1];
            float fp = g0[16 + jj1] + g1[16 + jj1] + xr[16 + jj1];
            float gp = g0[32 + jj1] + g1[32 + jj1] + xr[32 + jj1];
            float op = g0[48 + jj1] + g1[48 + jj1] + xr[48 + jj1];
            float ii = sigmoidf_fast(ip), ff = sigmoidf_fast(fp);
            float gg = tanhf_fast(gp),    oo = sigmoidf_fast(op);
            float cn = ff * creg1 + ii * gg;
            creg1 = cn;
            float hn = oo * tanhf_fast(cn);
            hN[b1 * HDIM + cta * 16 + jj1] = __float2half(hn);
            if (t == T_STEPS - 1) {
                out[HOFF + (size_t)b1 * HDIM + cta * 16 + jj1] = hn;
                out[COFF + (size_t)b1 * HDIM + cta * 16 + jj1] = cn;
            }
            e1 = __expf(hn);
        }
        {
            const float* g0 = &gsum[(size_t)b2 * GSTR];
            const float* g1 = &gsum[(size_t)(64 + b2) * GSTR];
            const float* xr = xp + (size_t)b2 * G4;
            float ip = g0[jj2]      + g1[jj2]      + xr[jj2];
            float fp = g0[16 + jj2] + g1[16 + jj2] + xr[16 + jj2];
            float gp = g0[32 + jj2] + g1[32 + jj2] + xr[32 + jj2];
            float op = g0[48 + jj2] + g1[48 + jj2] + xr[48 + jj2];
            float ii = sigmoidf_fast(ip), ff = sigmoidf_fast(fp);
            float gg = tanhf_fast(gp),    oo = sigmoidf_fast(op);
            float cn = ff * creg2 + ii * gg;
            creg2 = cn;
            float hn = oo * tanhf_fast(cn);
            hN[b2 * HDIM + cta * 16 + jj2] = __float2half(hn);
            if (t == T_STEPS - 1) {
                out[HOFF + (size_t)b2 * HDIM + cta * 16 + jj2] = hn;
                out[COFF + (size_t)b2 * HDIM + cta * 16 + jj2] = cn;
            }
            e2 = __expf(hn);
        }
        float v1 = e1, v2 = e2;
        #pragma unroll
        for (int o = 8; o > 0; o >>= 1) {
            v1 += __shfl_xor_sync(0xffffffffu, v1, o);
            v2 += __shfl_xor_sync(0xffffffffu, v2, o);
        }
        if ((lane & 15) == 0) {
            atomicAdd(&d_sum[t * BATCH + b1], v1);
            atomicAdd(&d_sum[t * BATCH + b2], v2);
        }

        bar_target += NCTAS;
        grid_barrier(bar_target);

        {
            float s1 = __ldcg(&d_sum[t * BATCH + b1]);
            float s2 = __ldcg(&d_sum[t * BATCH + b2]);
            out[(size_t)t * BATCH * HDIM + (size_t)b1 * HDIM + cta * 16 + jj1] = e1 * (1.0f / s1);
            out[(size_t)t * BATCH * HDIM + (size_t)b2 * HDIM + cta * 16 + jj2] = e2 * (1.0f / s2);
        }
    }
}

// ---------------- entry ----------------
extern "C" void kernel_launch(void* const* d_in, const int* in_sizes, int n_in,
                              void* d_out, int out_size)
{
    (void)in_sizes; (void)n_in; (void)out_size;
    const float* input = (const float*)d_in[0];
    const float* h0    = (const float*)d_in[1];
    const float* c0    = (const float*)d_in[2];
    const float* wih   = (const float*)d_in[3];
    const float* whh   = (const float*)d_in[4];
    const float* bih   = (const float*)d_in[5];
    const float* bhh   = (const float*)d_in[6];

    const int smem_bytes = 12 * TILEH * (int)sizeof(__half) + 2 * 64 * GSTR * (int)sizeof(float);
    cudaFuncSetAttribute(lstm_persistent_c0,
                         cudaFuncAttributeMaxDynamicSharedMemorySize, smem_bytes);

    prep_kernel<<<1024, 256>>>(input, h0, c0, wih, whh, bih, bhh);
    xproj_kernel<<<dim3(G4 / 64, (T_STEPS * BATCH) / 64), XTHREADS>>>();
    lstm_persistent_c0<<<NCTAS, PTHREADS, smem_bytes>>>((float*)d_out, c0);
}

// round 4
// speedup vs baseline: 1.9822x; 1.1893x over previous
#include <cuda_runtime.h>
#include <cuda_fp16.h>
#include <cstdint>

#define T_STEPS 256
#define BATCH   64
#define XDIM    512
#define HDIM    2048
#define G4      8192
#define NCTAS   128
#define PTHREADS 512
#define XTHREADS 256
#define KT      64                 // K-tile (halfs)
#define TILEHALFS (64*KT)          // 4096 halfs = 8192 B per 64x64 tile
#define STAGES  4
#define GSTR    68                 // gate smem row stride (floats)

// ---------------- device scratch ----------------
__device__ __align__(16) __half d_in16 [T_STEPS * BATCH * XDIM];
__device__ __align__(16) __half d_wih16[G4 * XDIM];
__device__ __align__(16) __half d_whh16[G4 * HDIM];
__device__ __align__(16) float  d_bsum [G4];
__device__ __align__(16) float  d_xproj[(size_t)T_STEPS * BATCH * G4];
__device__ __align__(16) __half d_h16  [2][BATCH * HDIM];
__device__ __align__(16) float  d_sum  [T_STEPS * BATCH];
__device__ unsigned d_bar;

// ---------------- helpers ----------------
__device__ __forceinline__ void mma16816(float* c,
    uint32_t a0, uint32_t a1, uint32_t a2, uint32_t a3,
    uint32_t b0, uint32_t b1)
{
    asm volatile(
        "mma.sync.aligned.m16n8k16.row.col.f32.f16.f16.f32 "
        "{%0,%1,%2,%3},{%4,%5,%6,%7},{%8,%9},{%0,%1,%2,%3};\n"
        : "+f"(c[0]), "+f"(c[1]), "+f"(c[2]), "+f"(c[3])
        : "r"(a0), "r"(a1), "r"(a2), "r"(a3), "r"(b0), "r"(b1));
}
__device__ __forceinline__ float sigmoidf_fast(float x) {
    return 1.0f / (1.0f + __expf(-x));
}
__device__ __forceinline__ float tanhf_fast(float x) {
    float e = __expf(2.0f * x);
    return 1.0f - 2.0f / (e + 1.0f);
}
__device__ __forceinline__ uint32_t smem_u32(const void* p) {
    return (uint32_t)__cvta_generic_to_shared(p);
}
// bit-rotate permutation of row&7: injective, splits chunk sets across banks
__device__ __forceinline__ int fperm(int r) { return ((r & 1) << 2) | ((r & 7) >> 1); }

#define CP16(dst_u32, src_ptr) \
    asm volatile("cp.async.cg.shared.global [%0], [%1], 16;\n" :: "r"(dst_u32), "l"(src_ptr))
#define CP_COMMIT() asm volatile("cp.async.commit_group;\n" ::: "memory")
#define CP_WAIT2()  asm volatile("cp.async.wait_group 2;\n" ::: "memory")

// row permutation: dst row (CTA-major, gate-interleaved) -> src gate row
__device__ __forceinline__ int perm_src_row(int r) {
    int cta = r >> 6;
    int ln  = r & 63;
    int gate = ln >> 4;
    int jj   = ln & 15;
    return gate * HDIM + cta * 16 + jj;
}

// ---------------- phase 0 ----------------
__global__ __launch_bounds__(256) void prep_kernel(
    const float* __restrict__ input, const float* __restrict__ h0,
    const float* __restrict__ c0,    const float* __restrict__ wih,
    const float* __restrict__ whh,   const float* __restrict__ bih,
    const float* __restrict__ bhh)
{
    (void)c0;
    const int i0 = blockIdx.x * blockDim.x + threadIdx.x;
    const int stride = gridDim.x * blockDim.x;
    if (i0 == 0) d_bar = 0u;
    for (int i = i0; i < T_STEPS * BATCH * XDIM; i += stride)
        d_in16[i] = __float2half(input[i]);
    for (int i = i0; i < G4 * XDIM; i += stride) {
        int r = i >> 9, k = i & (XDIM - 1);
        d_wih16[i] = __float2half(wih[perm_src_row(r) * XDIM + k]);
    }
    for (int i = i0; i < G4 * HDIM; i += stride) {
        int r = i >> 11, k = i & (HDIM - 1);
        d_whh16[i] = __float2half(whh[(size_t)perm_src_row(r) * HDIM + k]);
    }
    for (int i = i0; i < G4; i += stride) {
        int s = perm_src_row(i);
        d_bsum[i] = bih[s] + bhh[s];
    }
    for (int i = i0; i < BATCH * HDIM; i += stride)
        d_h16[0][i] = __float2half(h0[i]);
    for (int i = i0; i < T_STEPS * BATCH; i += stride)
        d_sum[i] = 0.0f;
}

// ---------------- phase 1: xproj (4-stage cp.async, swizzled) ----------------
__global__ __launch_bounds__(XTHREADS) void xproj_kernel()
{
    extern __shared__ __align__(16) char xsmem_raw[];
    __half* sAll = (__half*)xsmem_raw;
    __half* sA = sAll;                         // 4 stages
    __half* sB = sAll + STAGES * TILEHALFS;    // 4 stages

    const int tid  = threadIdx.x;
    const int lane = tid & 31, wid = tid >> 5;
    const int wm = wid >> 1, wn = wid & 1;
    const int gq = lane >> 2, tq = lane & 3;
    const int fp = fperm(gq);
    const int n0 = blockIdx.x * 64;
    const int m0 = blockIdx.y * 64;

    // load mapping
    const int lrow = tid >> 2, lch = tid & 3;
    const int fp_s = fperm(lrow);
    const uint32_t sAu = smem_u32(sA), sBu = smem_u32(sB);
    const uint32_t d0 = (uint32_t)(lrow * KT + ((lch ^ fp_s) * 8)) * 2;
    const uint32_t d1 = (uint32_t)(lrow * KT + (((lch + 4) ^ fp_s) * 8)) * 2;
    const int scol = lch * 8;

    const __half* Ag = d_in16  + (size_t)(m0 + lrow) * XDIM + scol;
    const __half* Bg = d_wih16 + (size_t)(n0 + lrow) * XDIM + scol;

    float acc[4][4];
    #pragma unroll
    for (int i = 0; i < 4; i++)
        #pragma unroll
        for (int j = 0; j < 4; j++) acc[i][j] = 0.0f;

    const int NITX = XDIM / KT;   // 8
    #pragma unroll
    for (int st = 0; st < 3; ++st) {
        const int kb = st * KT;
        CP16(sAu + (uint32_t)st * TILEHALFS * 2 + d0, Ag + kb);
        CP16(sAu + (uint32_t)st * TILEHALFS * 2 + d1, Ag + kb + 32);
        CP16(sBu + (uint32_t)st * TILEHALFS * 2 + d0, Bg + kb);
        CP16(sBu + (uint32_t)st * TILEHALFS * 2 + d1, Bg + kb + 32);
        CP_COMMIT();
    }

    const int rowA = wm * 16 + gq;
    #pragma unroll 1
    for (int it = 0; it < NITX; ++it) {
        CP_WAIT2();
        __syncthreads();
        const __half* At = sA + (it & 3) * TILEHALFS;
        const __half* Bt = sB + (it & 3) * TILEHALFS;
        #pragma unroll
        for (int k = 0; k < 4; ++k) {
            const int c0o = ((2 * k) ^ fp) * 8 + tq * 2;
            const int c1o = ((2 * k + 1) ^ fp) * 8 + tq * 2;
            uint32_t a0 = *(const uint32_t*)(At + rowA * KT + c0o);
            uint32_t a1 = *(const uint32_t*)(At + (rowA + 8) * KT + c0o);
            uint32_t a2 = *(const uint32_t*)(At + rowA * KT + c1o);
            uint32_t a3 = *(const uint32_t*)(At + (rowA + 8) * KT + c1o);
            #pragma unroll
            for (int nf = 0; nf < 4; nf++) {
                const int rowB = wn * 32 + nf * 8 + gq;
                uint32_t b0 = *(const uint32_t*)(Bt + rowB * KT + c0o);
                uint32_t b1 = *(const uint32_t*)(Bt + rowB * KT + c1o);
                mma16816(acc[nf], a0, a1, a2, a3, b0, b1);
            }
        }
        __syncthreads();
        const int nxt = it + 3;
        if (nxt < NITX) {
            const uint32_t so = (uint32_t)(nxt & 3) * TILEHALFS * 2;
            const int kb = nxt * KT;
            CP16(sAu + so + d0, Ag + kb);
            CP16(sAu + so + d1, Ag + kb + 32);
            CP16(sBu + so + d0, Bg + kb);
            CP16(sBu + so + d1, Bg + kb + 32);
        }
        CP_COMMIT();
    }

    #pragma unroll
    for (int nf = 0; nf < 4; nf++) {
        const int cb = n0 + wn * 32 + nf * 8 + tq * 2;
        const int r0 = m0 + wm * 16 + gq;
        float2 bsv = *(const float2*)(d_bsum + cb);
        float2 v0 = make_float2(acc[nf][0] + bsv.x, acc[nf][1] + bsv.y);
        float2 v1 = make_float2(acc[nf][2] + bsv.x, acc[nf][3] + bsv.y);
        *(float2*)(d_xproj + (size_t)r0 * G4 + cb)       = v0;
        *(float2*)(d_xproj + (size_t)(r0 + 8) * G4 + cb) = v1;
    }
}

// ---------------- grid barrier ----------------
__device__ __forceinline__ void grid_barrier(unsigned target)
{
    __syncthreads();
    if (threadIdx.x == 0) {
        __threadfence();
        atomicAdd(&d_bar, 1u);
        volatile unsigned* p = &d_bar;
        while (*p < target) { }
        __threadfence();
    }
    __syncthreads();
}

// ---------------- phase 2: persistent recurrent kernel ----------------
__global__ __launch_bounds__(PTHREADS, 1) void lstm_persistent_c0(
    float* __restrict__ out, const float* __restrict__ c0)
{
    extern __shared__ __align__(16) char smem_raw[];
    __half* sAll = (__half*)smem_raw;
    // [A g0 (4 stages)][A g1][B g0][B g1] then gsum
    float* gsum = (float*)(sAll + 16 * TILEHALFS);

    const int cta  = blockIdx.x;
    const int tid  = threadIdx.x;
    const int lane = tid & 31;
    const int g    = tid >> 8;
    const int gtid = tid & 255;
    const int gwid = gtid >> 5;
    const int wm = gwid >> 1, wn = gwid & 1;
    const int gq = lane >> 2, tq = lane & 3;
    const int fp = fperm(gq);
    const int n0 = cta * 64;
    const int KOFF = g * (HDIM / 2);
    const int NIT  = (HDIM / 2) / KT;   // 16

    __half* sA = sAll + (size_t)g * STAGES * TILEHALFS;
    __half* sB = sAll + 8 * TILEHALFS + (size_t)g * STAGES * TILEHALFS;
    const uint32_t sAu = smem_u32(sA), sBu = smem_u32(sB);

    // cp.async mapping
    const int lrow = gtid >> 2, lch = gtid & 3;
    const int fp_s = fperm(lrow);
    const uint32_t d0 = (uint32_t)(lrow * KT + ((lch ^ fp_s) * 8)) * 2;
    const uint32_t d1 = (uint32_t)(lrow * KT + (((lch + 4) ^ fp_s) * 8)) * 2;
    const int scol = lch * 8;
    const __half* Bg = d_whh16 + (size_t)(n0 + lrow) * HDIM + KOFF + scol;

    const size_t HOFF = (size_t)T_STEPS * BATCH * HDIM;
    const size_t COFF = HOFF + (size_t)BATCH * HDIM;

    const int i1 = tid,        b1 = i1 >> 4, jj1 = i1 & 15;
    const int i2 = tid + 512,  b2 = i2 >> 4, jj2 = i2 & 15;
    float creg1 = c0[b1 * HDIM + cta * 16 + jj1];
    float creg2 = c0[b2 * HDIM + cta * 16 + jj2];

    unsigned bar_target = 0;
    const int rowA = wm * 16 + gq;

#define ISSUE_STAGE(slot, kb, hptr) do {                                          \
        const __half* asrc_ = (hptr) + (size_t)lrow * HDIM + KOFF + (kb) + scol;  \
        const __half* bsrc_ = Bg + (kb);                                          \
        const uint32_t so_ = (uint32_t)(slot) * TILEHALFS * 2;                    \
        CP16(sAu + so_ + d0, asrc_);                                              \
        CP16(sAu + so_ + d1, asrc_ + 32);                                         \
        CP16(sBu + so_ + d0, bsrc_);                                              \
        CP16(sBu + so_ + d1, bsrc_ + 32);                                         \
        CP_COMMIT();                                                              \
    } while (0)

    // initial prologue (t = 0)
    {
        const __half* hbuf = d_h16[0];
        ISSUE_STAGE(0, 0 * KT, hbuf);
        ISSUE_STAGE(1, 1 * KT, hbuf);
        ISSUE_STAGE(2, 2 * KT, hbuf);
    }

    #pragma unroll 1
    for (int t = 0; t < T_STEPS; ++t) {
        const __half* hbuf = d_h16[t & 1];
        float acc[4][4];
        #pragma unroll
        for (int i = 0; i < 4; i++)
            #pragma unroll
            for (int j = 0; j < 4; j++) acc[i][j] = 0.0f;

        #pragma unroll 1
        for (int it = 0; it < NIT; ++it) {
            CP_WAIT2();
            asm volatile("bar.sync %0, 256;\n" :: "r"(g + 1) : "memory");
            const __half* At = sA + (it & 3) * TILEHALFS;
            const __half* Bt = sB + (it & 3) * TILEHALFS;
            #pragma unroll
            for (int k = 0; k < 4; ++k) {
                const int c0o = ((2 * k) ^ fp) * 8 + tq * 2;
                const int c1o = ((2 * k + 1) ^ fp) * 8 + tq * 2;
                uint32_t a0 = *(const uint32_t*)(At + rowA * KT + c0o);
                uint32_t a1 = *(const uint32_t*)(At + (rowA + 8) * KT + c0o);
                uint32_t a2 = *(const uint32_t*)(At + rowA * KT + c1o);
                uint32_t a3 = *(const uint32_t*)(At + (rowA + 8) * KT + c1o);
                #pragma unroll
                for (int nf = 0; nf < 4; nf++) {
                    const int rowB = wn * 32 + nf * 8 + gq;
                    uint32_t b0 = *(const uint32_t*)(Bt + rowB * KT + c0o);
                    uint32_t b1 = *(const uint32_t*)(Bt + rowB * KT + c1o);
                    mma16816(acc[nf], a0, a1, a2, a3, b0, b1);
                }
            }
            asm volatile("bar.sync %0, 256;\n" :: "r"(g + 1) : "memory");
            const int nxt = it + 3;
            if (nxt < NIT) {
                ISSUE_STAGE(nxt & 3, nxt * KT, hbuf);
            } else {
                CP_COMMIT();   // keep commit cadence for wait_group counting
            }
        }

        // epilogue: group partials -> SMEM
        #pragma unroll
        for (int nf = 0; nf < 4; nf++) {
            const int cb = wn * 32 + nf * 8 + tq * 2;
            const int r0 = wm * 16 + gq;
            *(float2*)&gsum[((size_t)g * 64 + r0) * GSTR + cb]     = make_float2(acc[nf][0], acc[nf][1]);
            *(float2*)&gsum[((size_t)g * 64 + r0 + 8) * GSTR + cb] = make_float2(acc[nf][2], acc[nf][3]);
        }
        __syncthreads();

        // pointwise LSTM + exp + partial softmax sum
        __half* hN = d_h16[(t + 1) & 1];
        const float* xp = d_xproj + (size_t)t * BATCH * G4 + n0;
        float e1, e2;
        {
            const float* g0 = &gsum[(size_t)b1 * GSTR];
            const float* g1 = &gsum[(size_t)(64 + b1) * GSTR];
            const float* xr = xp + (size_t)b1 * G4;
            float ip = g0[jj1]      + g1[jj1]      + xr[jj1];
            float fpv= g0[16 + jj1] + g1[16 + jj1] + xr[16 + jj1];
            float gp = g0[32 + jj1] + g1[32 + jj1] + xr[32 + jj1];
            float op = g0[48 + jj1] + g1[48 + jj1] + xr[48 + jj1];
            float ii = sigmoidf_fast(ip), ff = sigmoidf_fast(fpv);
            float gg = tanhf_fast(gp),    oo = sigmoidf_fast(op);
            float cn = ff * creg1 + ii * gg;
            creg1 = cn;
            float hn = oo * tanhf_fast(cn);
            hN[b1 * HDIM + cta * 16 + jj1] = __float2half(hn);
            if (t == T_STEPS - 1) {
                out[HOFF + (size_t)b1 * HDIM + cta * 16 + jj1] = hn;
                out[COFF + (size_t)b1 * HDIM + cta * 16 + jj1] = cn;
            }
            e1 = __expf(hn);
        }
        {
            const float* g0 = &gsum[(size_t)b2 * GSTR];
            const float* g1 = &gsum[(size_t)(64 + b2) * GSTR];
            const float* xr = xp + (size_t)b2 * G4;
            float ip = g0[jj2]      + g1[jj2]      + xr[jj2];
            float fpv= g0[16 + jj2] + g1[16 + jj2] + xr[16 + jj2];
            float gp = g0[32 + jj2] + g1[32 + jj2] + xr[32 + jj2];
            float op = g0[48 + jj2] + g1[48 + jj2] + xr[48 + jj2];
            float ii = sigmoidf_fast(ip), ff = sigmoidf_fast(fpv);
            float gg = tanhf_fast(gp),    oo = sigmoidf_fast(op);
            float cn = ff * creg2 + ii * gg;
            creg2 = cn;
            float hn = oo * tanhf_fast(cn);
            hN[b2 * HDIM + cta * 16 + jj2] = __float2half(hn);
            if (t == T_STEPS - 1) {
                out[HOFF + (size_t)b2 * HDIM + cta * 16 + jj2] = hn;
                out[COFF + (size_t)b2 * HDIM + cta * 16 + jj2] = cn;
            }
            e2 = __expf(hn);
        }
        float v1 = e1, v2 = e2;
        #pragma unroll
        for (int o = 8; o > 0; o >>= 1) {
            v1 += __shfl_xor_sync(0xffffffffu, v1, o);
            v2 += __shfl_xor_sync(0xffffffffu, v2, o);
        }
        if ((lane & 15) == 0) {
            atomicAdd(&d_sum[t * BATCH + b1], v1);
            atomicAdd(&d_sum[t * BATCH + b2], v2);
        }

        bar_target += NCTAS;
        grid_barrier(bar_target);

        // issue next step's prologue first (hides refill), then normalize y
        if (t + 1 < T_STEPS) {
            const __half* hnext = d_h16[(t + 1) & 1];
            ISSUE_STAGE(0, 0 * KT, hnext);
            ISSUE_STAGE(1, 1 * KT, hnext);
            ISSUE_STAGE(2, 2 * KT, hnext);
        }
        {
            float s1 = __ldcg(&d_sum[t * BATCH + b1]);
            float s2 = __ldcg(&d_sum[t * BATCH + b2]);
            out[(size_t)t * BATCH * HDIM + (size_t)b1 * HDIM + cta * 16 + jj1] = e1 * (1.0f / s1);
            out[(size_t)t * BATCH * HDIM + (size_t)b2 * HDIM + cta * 16 + jj2] = e2 * (1.0f / s2);
        }
    }
#undef ISSUE_STAGE
}

// ---------------- entry ----------------
extern "C" void kernel_launch(void* const* d_in, const int* in_sizes, int n_in,
                              void* d_out, int out_size)
{
    (void)in_sizes; (void)n_in; (void)out_size;
    const float* input = (const float*)d_in[0];
    const float* h0    = (const float*)d_in[1];
    const float* c0    = (const float*)d_in[2];
    const float* wih   = (const float*)d_in[3];
    const float* whh   = (const float*)d_in[4];
    const float* bih   = (const float*)d_in[5];
    const float* bhh   = (const float*)d_in[6];

    const int psmem = 16 * TILEHALFS * (int)sizeof(__half)
                    + 2 * 64 * GSTR * (int)sizeof(float);          // 165,888 B
    const int xsmem = 2 * STAGES * TILEHALFS * (int)sizeof(__half); // 65,536 B
    cudaFuncSetAttribute(lstm_persistent_c0,
                         cudaFuncAttributeMaxDynamicSharedMemorySize, psmem);
    cudaFuncSetAttribute(xproj_kernel,
                         cudaFuncAttributeMaxDynamicSharedMemorySize, xsmem);

    prep_kernel<<<1024, 256>>>(input, h0, c0, wih, whh, bih, bhh);
    xproj_kernel<<<dim3(G4 / 64, (T_STEPS * BATCH) / 64), XTHREADS, xsmem>>>();
    lstm_persistent_c0<<<NCTAS, PTHREADS, psmem>>>((float*)d_out, c0);
}

// round 6
// speedup vs baseline: 2.2420x; 1.1311x over previous
#include <cuda_runtime.h>
#include <cuda_fp16.h>
#include <cstdint>

#define T_STEPS 256
#define BATCH   64
#define XDIM    512
#define HDIM    2048
#define G4      8192
#define NCTAS   128
#define PTHREADS 512
#define XTHREADS 256
#define KT      64                 // K-tile per stage (halfs) = 128 B rows
#define TILEHALFS (64*KT)
#define STAGES  4
#define ASTG    8192               // stage tile bytes (64 rows * 128 B)
#define GSTR    66                 // gsum row stride (floats)
#define GSLAB   (64*GSTR)          // floats per slab

// persistent smem layout (bytes)
#define OFF_SB   (8*ASTG)                    // 65536  (A: 2 groups * 4 stages)
#define OFF_GSUM (OFF_SB + 8*ASTG)           // 131072 (B same size)
#define PSMEM    (OFF_GSUM + 4*GSLAB*4)      // + 4 slabs of 64x66 floats

// ---------------- device scratch ----------------
__device__ __align__(16) __half d_in16 [T_STEPS * BATCH * XDIM];
__device__ __align__(16) __half d_wih16[G4 * XDIM];
__device__ __align__(16) __half d_whh16[G4 * HDIM];
__device__ __align__(16) float  d_bsum [G4];
__device__ __align__(16) float  d_xproj[(size_t)T_STEPS * BATCH * G4];
__device__ __align__(16) __half d_h16  [2][BATCH * HDIM];
__device__ __align__(16) float  d_sum  [T_STEPS * BATCH];
__device__ unsigned d_bar;

// ---------------- helpers ----------------
__device__ __forceinline__ void mma16816(float* c,
    uint32_t a0, uint32_t a1, uint32_t a2, uint32_t a3,
    uint32_t b0, uint32_t b1)
{
    asm volatile(
        "mma.sync.aligned.m16n8k16.row.col.f32.f16.f16.f32 "
        "{%0,%1,%2,%3},{%4,%5,%6,%7},{%8,%9},{%0,%1,%2,%3};\n"
        : "+f"(c[0]), "+f"(c[1]), "+f"(c[2]), "+f"(c[3])
        : "r"(a0), "r"(a1), "r"(a2), "r"(a3), "r"(b0), "r"(b1));
}
#define LDSM4(r0, r1, r2, r3, addr) \
    asm volatile("ldmatrix.sync.aligned.m8n8.x4.shared.b16 {%0,%1,%2,%3}, [%4];" \
        : "=r"(r0), "=r"(r1), "=r"(r2), "=r"(r3) : "r"(addr))

__device__ __forceinline__ float sigmoidf_fast(float x) {
    return 1.0f / (1.0f + __expf(-x));
}
__device__ __forceinline__ float tanhf_fast(float x) {
    float e = __expf(2.0f * x);
    return 1.0f - 2.0f / (e + 1.0f);
}
__device__ __forceinline__ uint32_t smem_u32(const void* p) {
    return (uint32_t)__cvta_generic_to_shared(p);
}
__device__ __forceinline__ int fperm(int r) { return ((r & 1) << 2) | ((r & 7) >> 1); }

#define CP16(dst_u32, src_ptr) \
    asm volatile("cp.async.cg.shared.global [%0], [%1], 16;\n" :: "r"(dst_u32), "l"(src_ptr))
#define CP_COMMIT() asm volatile("cp.async.commit_group;\n" ::: "memory")
#define CP_WAIT2()  asm volatile("cp.async.wait_group 2;\n" ::: "memory")

// row permutation: dst row (CTA-major: cta*64 + gate*16 + jj) -> src gate row
__device__ __forceinline__ int perm_src_row(int r) {
    int cta = r >> 6;
    int ln  = r & 63;
    int gate = ln >> 4;
    int jj   = ln & 15;
    return gate * HDIM + cta * 16 + jj;
}

// ---------------- phase 0 ----------------
__global__ __launch_bounds__(256) void prep_kernel(
    const float* __restrict__ input, const float* __restrict__ h0,
    const float* __restrict__ c0,    const float* __restrict__ wih,
    const float* __restrict__ whh,   const float* __restrict__ bih,
    const float* __restrict__ bhh)
{
    (void)c0;
    const int i0 = blockIdx.x * blockDim.x + threadIdx.x;
    const int stride = gridDim.x * blockDim.x;
    if (i0 == 0) d_bar = 0u;
    for (int i = i0; i < T_STEPS * BATCH * XDIM; i += stride)
        d_in16[i] = __float2half(input[i]);
    for (int i = i0; i < G4 * XDIM; i += stride) {
        int r = i >> 9, k = i & (XDIM - 1);
        d_wih16[i] = __float2half(wih[perm_src_row(r) * XDIM + k]);
    }
    for (int i = i0; i < G4 * HDIM; i += stride) {
        int r = i >> 11, k = i & (HDIM - 1);
        d_whh16[i] = __float2half(whh[(size_t)perm_src_row(r) * HDIM + k]);
    }
    for (int i = i0; i < G4; i += stride) {
        int s = perm_src_row(i);
        d_bsum[i] = bih[s] + bhh[s];
    }
    for (int i = i0; i < BATCH * HDIM; i += stride)
        d_h16[0][i] = __float2half(h0[i]);
    for (int i = i0; i < T_STEPS * BATCH; i += stride)
        d_sum[i] = 0.0f;
}

// ---------------- phase 1: xproj (R4 pipeline, unchanged) ----------------
__global__ __launch_bounds__(XTHREADS) void xproj_kernel()
{
    extern __shared__ __align__(16) char xsmem_raw[];
    __half* sAll = (__half*)xsmem_raw;
    __half* sA = sAll;
    __half* sB = sAll + STAGES * TILEHALFS;

    const int tid  = threadIdx.x;
    const int lane = tid & 31, wid = tid >> 5;
    const int wm = wid >> 1, wn = wid & 1;
    const int gq = lane >> 2, tq = lane & 3;
    const int fp = fperm(gq);
    const int n0 = blockIdx.x * 64;
    const int m0 = blockIdx.y * 64;

    const int lrow = tid >> 2, lch = tid & 3;
    const int fp_s = fperm(lrow);
    const uint32_t sAu = smem_u32(sA), sBu = smem_u32(sB);
    const uint32_t d0 = (uint32_t)(lrow * KT + ((lch ^ fp_s) * 8)) * 2;
    const uint32_t d1 = (uint32_t)(lrow * KT + (((lch + 4) ^ fp_s) * 8)) * 2;
    const int scol = lch * 8;

    const __half* Ag = d_in16  + (size_t)(m0 + lrow) * XDIM + scol;
    const __half* Bg = d_wih16 + (size_t)(n0 + lrow) * XDIM + scol;

    float acc[4][4];
    #pragma unroll
    for (int i = 0; i < 4; i++)
        #pragma unroll
        for (int j = 0; j < 4; j++) acc[i][j] = 0.0f;

    const int NITX = XDIM / KT;
    #pragma unroll
    for (int st = 0; st < 3; ++st) {
        const int kb = st * KT;
        CP16(sAu + (uint32_t)st * TILEHALFS * 2 + d0, Ag + kb);
        CP16(sAu + (uint32_t)st * TILEHALFS * 2 + d1, Ag + kb + 32);
        CP16(sBu + (uint32_t)st * TILEHALFS * 2 + d0, Bg + kb);
        CP16(sBu + (uint32_t)st * TILEHALFS * 2 + d1, Bg + kb + 32);
        CP_COMMIT();
    }

    const int rowA = wm * 16 + gq;
    #pragma unroll 1
    for (int it = 0; it < NITX; ++it) {
        CP_WAIT2();
        __syncthreads();
        const __half* At = sA + (it & 3) * TILEHALFS;
        const __half* Bt = sB + (it & 3) * TILEHALFS;
        #pragma unroll
        for (int k = 0; k < 4; ++k) {
            const int c0o = ((2 * k) ^ fp) * 8 + tq * 2;
            const int c1o = ((2 * k + 1) ^ fp) * 8 + tq * 2;
            uint32_t a0 = *(const uint32_t*)(At + rowA * KT + c0o);
            uint32_t a1 = *(const uint32_t*)(At + (rowA + 8) * KT + c0o);
            uint32_t a2 = *(const uint32_t*)(At + rowA * KT + c1o);
            uint32_t a3 = *(const uint32_t*)(At + (rowA + 8) * KT + c1o);
            #pragma unroll
            for (int nf = 0; nf < 4; nf++) {
                const int rowB = wn * 32 + nf * 8 + gq;
                uint32_t b0 = *(const uint32_t*)(Bt + rowB * KT + c0o);
                uint32_t b1 = *(const uint32_t*)(Bt + rowB * KT + c1o);
                mma16816(acc[nf], a0, a1, a2, a3, b0, b1);
            }
        }
        __syncthreads();
        const int nxt = it + 3;
        if (nxt < NITX) {
            const uint32_t so = (uint32_t)(nxt & 3) * TILEHALFS * 2;
            const int kb = nxt * KT;
            CP16(sAu + so + d0, Ag + kb);
            CP16(sAu + so + d1, Ag + kb + 32);
            CP16(sBu + so + d0, Bg + kb);
            CP16(sBu + so + d1, Bg + kb + 32);
        }
        CP_COMMIT();
    }

    #pragma unroll
    for (int nf = 0; nf < 4; nf++) {
        const int cb = n0 + wn * 32 + nf * 8 + tq * 2;
        const int r0 = m0 + wm * 16 + gq;
        float2 bsv = *(const float2*)(d_bsum + cb);
        float2 v0 = make_float2(acc[nf][0] + bsv.x, acc[nf][1] + bsv.y);
        float2 v1 = make_float2(acc[nf][2] + bsv.x, acc[nf][3] + bsv.y);
        *(float2*)(d_xproj + (size_t)r0 * G4 + cb)       = v0;
        *(float2*)(d_xproj + (size_t)(r0 + 8) * G4 + cb) = v1;
    }
}

// ---------------- grid barrier (128 CTAs co-resident) ----------------
__device__ __forceinline__ void grid_barrier(unsigned target)
{
    __syncthreads();
    if (threadIdx.x == 0) {
        __threadfence();
        atomicAdd(&d_bar, 1u);
        volatile unsigned* p = &d_bar;
        while (*p < target) { }
        __threadfence();
    }
    __syncthreads();
}

// ---------------- phase 2: persistent recurrent kernel (ldmatrix + 2x2x2) ----
__global__ __launch_bounds__(PTHREADS, 1) void lstm_persistent_c0(
    float* __restrict__ out, const float* __restrict__ c0)
{
    extern __shared__ __align__(1024) char smem_raw[];
    const uint32_t sbase = smem_u32(smem_raw);
    float* gsum = (float*)(smem_raw + OFF_GSUM);

    const int cta  = blockIdx.x;
    const int tid  = threadIdx.x;
    const int lane = tid & 31;
    const int g    = tid >> 8;              // K-half group (0,1)
    const int gtid = tid & 255;
    const int gwid = gtid >> 5;             // warp in group 0..7
    const int wm = gwid & 1;                // m half (batch 32)
    const int wn = (gwid >> 1) & 1;         // n half (gate 32)
    const int wk = gwid >> 2;               // k quarter within group
    const int gq = lane >> 2, tq = lane & 3;
    const int n0 = cta * 64;                // permuted gate-row base
    const int KOFF = g * (HDIM / 2);
    const int NIT  = (HDIM / 2) / KT;       // 16

    // tile bases: A tiles [g*4+st], B tiles after OFF_SB
    const uint32_t aGrp = sbase + (uint32_t)g * 4 * ASTG;
    const uint32_t bGrp = sbase + OFF_SB + (uint32_t)g * 4 * ASTG;

    // cp.async load mapping (256 threads per group fill 8KB A + 8KB B)
    const int lrow = gtid >> 2, lch = gtid & 3;
    const int fp_s = fperm(lrow);
    const uint32_t d0 = (uint32_t)(lrow * 128 + ((lch ^ fp_s) << 4));
    const uint32_t d1 = (uint32_t)(lrow * 128 + (((lch + 4) ^ fp_s) << 4));
    const int scol = lch * 8;
    const __half* Bg = d_whh16 + (size_t)(n0 + lrow) * HDIM + KOFF + scol;

    // ldmatrix addressing
    const int fp_l = fperm(lane & 7);
    const uint32_t rowA0 = (uint32_t)((wm * 32 + (lane & 15)) * 128);
    const uint32_t rowA1 = rowA0 + 16 * 128;
    const uint32_t rowB0 = (uint32_t)((wn * 32 + ((lane >> 4) & 1) * 8 + (lane & 7)) * 128);
    const uint32_t rowB1 = rowB0 + 16 * 128;
    const int khA = (lane >> 4) & 1;
    const int khB = (lane >> 3) & 1;
    const int kb16 = wk * 2;                 // warp's first k16 within stage

    const size_t HOFF = (size_t)T_STEPS * BATCH * HDIM;
    const size_t COFF = HOFF + (size_t)BATCH * HDIM;

    // pointwise mapping (R4): two (b, jj) items per thread
    const int b1 = tid >> 4,        jj1 = tid & 15;
    const int b2 = 32 + (tid >> 4), jj2 = jj1;
    float creg1 = c0[b1 * HDIM + cta * 16 + jj1];
    float creg2 = c0[b2 * HDIM + cta * 16 + jj2];

    unsigned bar_target = 0;

#define ISSUE(SLOT, KB, HB) do {                                              \
        const __half* asrc_ = (HB) + (size_t)lrow * HDIM + KOFF + (KB) + scol;\
        const __half* bsrc_ = Bg + (KB);                                      \
        const uint32_t ao_ = aGrp + (uint32_t)(SLOT) * ASTG;                  \
        const uint32_t bo_ = bGrp + (uint32_t)(SLOT) * ASTG;                  \
        CP16(ao_ + d0, asrc_);                                                \
        CP16(ao_ + d1, asrc_ + 32);                                           \
        CP16(bo_ + d0, bsrc_);                                                \
        CP16(bo_ + d1, bsrc_ + 32);                                           \
        CP_COMMIT();                                                          \
    } while (0)

    // initial prologue (t = 0)
    {
        const __half* hbuf = d_h16[0];
        ISSUE(0, 0 * KT, hbuf);
        ISSUE(1, 1 * KT, hbuf);
        ISSUE(2, 2 * KT, hbuf);
    }

    #pragma unroll 1
    for (int t = 0; t < T_STEPS; ++t) {
        const __half* hbuf = d_h16[t & 1];
        float acc[2][4][4];
        #pragma unroll
        for (int i = 0; i < 2; i++)
            #pragma unroll
            for (int j = 0; j < 4; j++)
                #pragma unroll
                for (int q = 0; q < 4; q++) acc[i][j][q] = 0.0f;

        #pragma unroll 4
        for (int it = 0; it < NIT; ++it) {
            CP_WAIT2();
            asm volatile("bar.sync %0, 256;\n" :: "r"(g + 1) : "memory");
            const uint32_t At = aGrp + (uint32_t)(it & 3) * ASTG;
            const uint32_t Bt = bGrp + (uint32_t)(it & 3) * ASTG;
            #pragma unroll
            for (int kc = 0; kc < 2; ++kc) {
                const uint32_t ccA = (uint32_t)((((kb16 + kc) << 1) | khA) ^ fp_l) << 4;
                const uint32_t ccB = (uint32_t)((((kb16 + kc) << 1) | khB) ^ fp_l) << 4;
                uint32_t a0[4], a1[4], bb0[4], bb1[4];
                LDSM4(a0[0], a0[1], a0[2], a0[3], At + rowA0 + ccA);
                LDSM4(a1[0], a1[1], a1[2], a1[3], At + rowA1 + ccA);
                LDSM4(bb0[0], bb0[1], bb0[2], bb0[3], Bt + rowB0 + ccB);
                LDSM4(bb1[0], bb1[1], bb1[2], bb1[3], Bt + rowB1 + ccB);
                mma16816(acc[0][0], a0[0], a0[1], a0[2], a0[3], bb0[0], bb0[1]);
                mma16816(acc[0][1], a0[0], a0[1], a0[2], a0[3], bb0[2], bb0[3]);
                mma16816(acc[0][2], a0[0], a0[1], a0[2], a0[3], bb1[0], bb1[1]);
                mma16816(acc[0][3], a0[0], a0[1], a0[2], a0[3], bb1[2], bb1[3]);
                mma16816(acc[1][0], a1[0], a1[1], a1[2], a1[3], bb0[0], bb0[1]);
                mma16816(acc[1][1], a1[0], a1[1], a1[2], a1[3], bb0[2], bb0[3]);
                mma16816(acc[1][2], a1[0], a1[1], a1[2], a1[3], bb1[0], bb1[1]);
                mma16816(acc[1][3], a1[0], a1[1], a1[2], a1[3], bb1[2], bb1[3]);
            }
            const int nxt = it + 3;
            if (nxt < NIT) {
                ISSUE(nxt & 3, nxt * KT, hbuf);
            } else {
                CP_COMMIT();
            }
        }

        // epilogue: write this warp's partial slab (slab = g*2 + wk)
        {
            float* gs = gsum + (size_t)(g * 2 + wk) * GSLAB;
            #pragma unroll
            for (int mf = 0; mf < 2; ++mf) {
                const int row = wm * 32 + mf * 16 + gq;
                #pragma unroll
                for (int nf = 0; nf < 4; ++nf) {
                    const int col = wn * 32 + nf * 8 + tq * 2;
                    *(float2*)&gs[row * GSTR + col] =
                        make_float2(acc[mf][nf][0], acc[mf][nf][1]);
                    *(float2*)&gs[(row + 8) * GSTR + col] =
                        make_float2(acc[mf][nf][2], acc[mf][nf][3]);
                }
            }
        }
        __syncthreads();

        // pointwise LSTM + exp + partial softmax sum
        __half* hN = d_h16[(t + 1) & 1];
        const float* xp = d_xproj + (size_t)t * BATCH * G4 + n0;
        float e1, e2;
        {
            const float* gb = gsum + (size_t)b1 * GSTR;
            const float* xr = xp + (size_t)b1 * G4;
            float ip = gb[jj1] + gb[GSLAB + jj1] + gb[2*GSLAB + jj1] + gb[3*GSLAB + jj1] + xr[jj1];
            float fpv= gb[16+jj1] + gb[GSLAB+16+jj1] + gb[2*GSLAB+16+jj1] + gb[3*GSLAB+16+jj1] + xr[16+jj1];
            float gp = gb[32+jj1] + gb[GSLAB+32+jj1] + gb[2*GSLAB+32+jj1] + gb[3*GSLAB+32+jj1] + xr[32+jj1];
            float op = gb[48+jj1] + gb[GSLAB+48+jj1] + gb[2*GSLAB+48+jj1] + gb[3*GSLAB+48+jj1] + xr[48+jj1];
            float ii = sigmoidf_fast(ip), ff = sigmoidf_fast(fpv);
            float gg = tanhf_fast(gp),    oo = sigmoidf_fast(op);
            float cn = ff * creg1 + ii * gg;
            creg1 = cn;
            float hn = oo * tanhf_fast(cn);
            hN[b1 * HDIM + cta * 16 + jj1] = __float2half(hn);
            if (t == T_STEPS - 1) {
                out[HOFF + (size_t)b1 * HDIM + cta * 16 + jj1] = hn;
                out[COFF + (size_t)b1 * HDIM + cta * 16 + jj1] = cn;
            }
            e1 = __expf(hn);
        }
        {
            const float* gb = gsum + (size_t)b2 * GSTR;
            const float* xr = xp + (size_t)b2 * G4;
            float ip = gb[jj2] + gb[GSLAB + jj2] + gb[2*GSLAB + jj2] + gb[3*GSLAB + jj2] + xr[jj2];
            float fpv= gb[16+jj2] + gb[GSLAB+16+jj2] + gb[2*GSLAB+16+jj2] + gb[3*GSLAB+16+jj2] + xr[16+jj2];
            float gp = gb[32+jj2] + gb[GSLAB+32+jj2] + gb[2*GSLAB+32+jj2] + gb[3*GSLAB+32+jj2] + xr[32+jj2];
            float op = gb[48+jj2] + gb[GSLAB+48+jj2] + gb[2*GSLAB+48+jj2] + gb[3*GSLAB+48+jj2] + xr[48+jj2];
            float ii = sigmoidf_fast(ip), ff = sigmoidf_fast(fpv);
            float gg = tanhf_fast(gp),    oo = sigmoidf_fast(op);
            float cn = ff * creg2 + ii * gg;
            creg2 = cn;
            float hn = oo * tanhf_fast(cn);
            hN[b2 * HDIM + cta * 16 + jj2] = __float2half(hn);
            if (t == T_STEPS - 1) {
                out[HOFF + (size_t)b2 * HDIM + cta * 16 + jj2] = hn;
                out[COFF + (size_t)b2 * HDIM + cta * 16 + jj2] = cn;
            }
            e2 = __expf(hn);
        }
        float v1 = e1, v2 = e2;
        #pragma unroll
        for (int o = 8; o > 0; o >>= 1) {
            v1 += __shfl_xor_sync(0xffffffffu, v1, o);
            v2 += __shfl_xor_sync(0xffffffffu, v2, o);
        }
        if ((lane & 15) == 0) {
            atomicAdd(&d_sum[t * BATCH + b1], v1);
            atomicAdd(&d_sum[t * BATCH + b2], v2);
        }

        bar_target += NCTAS;
        grid_barrier(bar_target);

        // next step's prologue first (hide refill), then normalize y
        if (t + 1 < T_STEPS) {
            const __half* hnext = d_h16[(t + 1) & 1];
            ISSUE(0, 0 * KT, hnext);
            ISSUE(1, 1 * KT, hnext);
            ISSUE(2, 2 * KT, hnext);
        }
        {
            float s1 = __ldcg(&d_sum[t * BATCH + b1]);
            float s2 = __ldcg(&d_sum[t * BATCH + b2]);
            out[(size_t)t * BATCH * HDIM + (size_t)b1 * HDIM + cta * 16 + jj1] = e1 * (1.0f / s1);
            out[(size_t)t * BATCH * HDIM + (size_t)b2 * HDIM + cta * 16 + jj2] = e2 * (1.0f / s2);
        }
    }
#undef ISSUE
}

// ---------------- entry ----------------
extern "C" void kernel_launch(void* const* d_in, const int* in_sizes, int n_in,
                              void* d_out, int out_size)
{
    (void)in_sizes; (void)n_in; (void)out_size;
    const float* input = (const float*)d_in[0];
    const float* h0    = (const float*)d_in[1];
    const float* c0    = (const float*)d_in[2];
    const float* wih   = (const float*)d_in[3];
    const float* whh   = (const float*)d_in[4];
    const float* bih   = (const float*)d_in[5];
    const float* bhh   = (const float*)d_in[6];

    const int xsmem = 2 * STAGES * TILEHALFS * (int)sizeof(__half);
    cudaFuncSetAttribute(xproj_kernel,
                         cudaFuncAttributeMaxDynamicSharedMemorySize, xsmem);
    cudaFuncSetAttribute(lstm_persistent_c0,
                         cudaFuncAttributeMaxDynamicSharedMemorySize, PSMEM);

    prep_kernel<<<1024, 256>>>(input, h0, c0, wih, whh, bih, bhh);
    xproj_kernel<<<dim3(G4 / 64, (T_STEPS * BATCH) / 64), XTHREADS, xsmem>>>();
    lstm_persistent_c0<<<NCTAS, PTHREADS, PSMEM>>>((float*)d_out, c0);
}

// round 7
// speedup vs baseline: 2.3096x; 1.0301x over previous
#include <cuda_runtime.h>
#include <cuda_fp16.h>
#include <cstdint>

#define T_STEPS 256
#define BATCH   64
#define XDIM    512
#define HDIM    2048
#define G4      8192
#define NCTAS   128
#define PTHREADS 512
#define XTHREADS 256
#define KT      64                 // K-tile per stage (halfs) = 128 B rows
#define TILEHALFS (64*KT)
#define STAGES  4
#define ASTG    8192               // stage tile bytes (64 rows * 128 B)
#define GSTR    66                 // gsum row stride (floats)
#define GSLAB   (64*GSTR)          // floats per slab

// persistent smem layout (bytes)
#define OFF_SB   (8*ASTG)                    // 65536  (A: 2 groups * 4 stages)
#define OFF_GSUM (OFF_SB + 8*ASTG)           // 131072 (B same size)
#define PSMEM    (OFF_GSUM + 4*GSLAB*4)      // + 4 slabs of 64x66 floats

// ---------------- device scratch ----------------
__device__ __align__(16) __half d_in16 [T_STEPS * BATCH * XDIM];
__device__ __align__(16) __half d_wih16[G4 * XDIM];
__device__ __align__(16) __half d_whh16[G4 * HDIM];
__device__ __align__(16) float  d_bsum [G4];
__device__ __align__(16) float  d_xproj[(size_t)T_STEPS * BATCH * G4];
__device__ __align__(16) __half d_h16  [2][BATCH * HDIM];
__device__ __align__(16) float  d_sum  [T_STEPS * BATCH];
__device__ unsigned d_bar;

// ---------------- helpers ----------------
__device__ __forceinline__ void mma16816(float* c,
    uint32_t a0, uint32_t a1, uint32_t a2, uint32_t a3,
    uint32_t b0, uint32_t b1)
{
    asm volatile(
        "mma.sync.aligned.m16n8k16.row.col.f32.f16.f16.f32 "
        "{%0,%1,%2,%3},{%4,%5,%6,%7},{%8,%9},{%0,%1,%2,%3};\n"
        : "+f"(c[0]), "+f"(c[1]), "+f"(c[2]), "+f"(c[3])
        : "r"(a0), "r"(a1), "r"(a2), "r"(a3), "r"(b0), "r"(b1));
}
#define LDSM4(r0, r1, r2, r3, addr) \
    asm volatile("ldmatrix.sync.aligned.m8n8.x4.shared.b16 {%0,%1,%2,%3}, [%4];" \
        : "=r"(r0), "=r"(r1), "=r"(r2), "=r"(r3) : "r"(addr))

// HW tanh: 1 MUFU op, max rel err ~2^-11
__device__ __forceinline__ float tanh_hw(float x) {
    float y;
    asm("tanh.approx.f32 %0, %1;" : "=f"(y) : "f"(x));
    return y;
}
// sigmoid(x) = 0.5 + 0.5*tanh(x/2): 1 MUFU + 2 FMA
__device__ __forceinline__ float sigmoid_hw(float x) {
    return fmaf(tanh_hw(0.5f * x), 0.5f, 0.5f);
}
// exp(x) = ex2(x * log2e): 1 MUFU + 1 FMUL
__device__ __forceinline__ float exp_hw(float x) {
    float y;
    asm("ex2.approx.ftz.f32 %0, %1;" : "=f"(y) : "f"(x * 1.4426950408889634f));
    return y;
}

__device__ __forceinline__ uint32_t smem_u32(const void* p) {
    return (uint32_t)__cvta_generic_to_shared(p);
}
__device__ __forceinline__ int fperm(int r) { return ((r & 1) << 2) | ((r & 7) >> 1); }

#define CP16(dst_u32, src_ptr) \
    asm volatile("cp.async.cg.shared.global [%0], [%1], 16;\n" :: "r"(dst_u32), "l"(src_ptr))
#define CP_COMMIT() asm volatile("cp.async.commit_group;\n" ::: "memory")
#define CP_WAIT2()  asm volatile("cp.async.wait_group 2;\n" ::: "memory")

// row permutation: dst row (CTA-major: cta*64 + gate*16 + jj) -> src gate row
__device__ __forceinline__ int perm_src_row(int r) {
    int cta = r >> 6;
    int ln  = r & 63;
    int gate = ln >> 4;
    int jj   = ln & 15;
    return gate * HDIM + cta * 16 + jj;
}

// ---------------- phase 0 ----------------
__global__ __launch_bounds__(256) void prep_kernel(
    const float* __restrict__ input, const float* __restrict__ h0,
    const float* __restrict__ c0,    const float* __restrict__ wih,
    const float* __restrict__ whh,   const float* __restrict__ bih,
    const float* __restrict__ bhh)
{
    (void)c0;
    const int i0 = blockIdx.x * blockDim.x + threadIdx.x;
    const int stride = gridDim.x * blockDim.x;
    if (i0 == 0) d_bar = 0u;
    for (int i = i0; i < T_STEPS * BATCH * XDIM; i += stride)
        d_in16[i] = __float2half(input[i]);
    for (int i = i0; i < G4 * XDIM; i += stride) {
        int r = i >> 9, k = i & (XDIM - 1);
        d_wih16[i] = __float2half(wih[perm_src_row(r) * XDIM + k]);
    }
    for (int i = i0; i < G4 * HDIM; i += stride) {
        int r = i >> 11, k = i & (HDIM - 1);
        d_whh16[i] = __float2half(whh[(size_t)perm_src_row(r) * HDIM + k]);
    }
    for (int i = i0; i < G4; i += stride) {
        int s = perm_src_row(i);
        d_bsum[i] = bih[s] + bhh[s];
    }
    for (int i = i0; i < BATCH * HDIM; i += stride)
        d_h16[0][i] = __float2half(h0[i]);
    for (int i = i0; i < T_STEPS * BATCH; i += stride)
        d_sum[i] = 0.0f;
}

// ---------------- phase 1: xproj ----------------
__global__ __launch_bounds__(XTHREADS) void xproj_kernel()
{
    extern __shared__ __align__(16) char xsmem_raw[];
    __half* sAll = (__half*)xsmem_raw;
    __half* sA = sAll;
    __half* sB = sAll + STAGES * TILEHALFS;

    const int tid  = threadIdx.x;
    const int lane = tid & 31, wid = tid >> 5;
    const int wm = wid >> 1, wn = wid & 1;
    const int gq = lane >> 2, tq = lane & 3;
    const int fp = fperm(gq);
    const int n0 = blockIdx.x * 64;
    const int m0 = blockIdx.y * 64;

    const int lrow = tid >> 2, lch = tid & 3;
    const int fp_s = fperm(lrow);
    const uint32_t sAu = smem_u32(sA), sBu = smem_u32(sB);
    const uint32_t d0 = (uint32_t)(lrow * KT + ((lch ^ fp_s) * 8)) * 2;
    const uint32_t d1 = (uint32_t)(lrow * KT + (((lch + 4) ^ fp_s) * 8)) * 2;
    const int scol = lch * 8;

    const __half* Ag = d_in16  + (size_t)(m0 + lrow) * XDIM + scol;
    const __half* Bg = d_wih16 + (size_t)(n0 + lrow) * XDIM + scol;

    float acc[4][4];
    #pragma unroll
    for (int i = 0; i < 4; i++)
        #pragma unroll
        for (int j = 0; j < 4; j++) acc[i][j] = 0.0f;

    const int NITX = XDIM / KT;
    #pragma unroll
    for (int st = 0; st < 3; ++st) {
        const int kb = st * KT;
        CP16(sAu + (uint32_t)st * TILEHALFS * 2 + d0, Ag + kb);
        CP16(sAu + (uint32_t)st * TILEHALFS * 2 + d1, Ag + kb + 32);
        CP16(sBu + (uint32_t)st * TILEHALFS * 2 + d0, Bg + kb);
        CP16(sBu + (uint32_t)st * TILEHALFS * 2 + d1, Bg + kb + 32);
        CP_COMMIT();
    }

    const int rowA = wm * 16 + gq;
    #pragma unroll 1
    for (int it = 0; it < NITX; ++it) {
        CP_WAIT2();
        __syncthreads();
        const __half* At = sA + (it & 3) * TILEHALFS;
        const __half* Bt = sB + (it & 3) * TILEHALFS;
        #pragma unroll
        for (int k = 0; k < 4; ++k) {
            const int c0o = ((2 * k) ^ fp) * 8 + tq * 2;
            const int c1o = ((2 * k + 1) ^ fp) * 8 + tq * 2;
            uint32_t a0 = *(const uint32_t*)(At + rowA * KT + c0o);
            uint32_t a1 = *(const uint32_t*)(At + (rowA + 8) * KT + c0o);
            uint32_t a2 = *(const uint32_t*)(At + rowA * KT + c1o);
            uint32_t a3 = *(const uint32_t*)(At + (rowA + 8) * KT + c1o);
            #pragma unroll
            for (int nf = 0; nf < 4; nf++) {
                const int rowB = wn * 32 + nf * 8 + gq;
                uint32_t b0 = *(const uint32_t*)(Bt + rowB * KT + c0o);
                uint32_t b1 = *(const uint32_t*)(Bt + rowB * KT + c1o);
                mma16816(acc[nf], a0, a1, a2, a3, b0, b1);
            }
        }
        __syncthreads();
        const int nxt = it + 3;
        if (nxt < NITX) {
            const uint32_t so = (uint32_t)(nxt & 3) * TILEHALFS * 2;
            const int kb = nxt * KT;
            CP16(sAu + so + d0, Ag + kb);
            CP16(sAu + so + d1, Ag + kb + 32);
            CP16(sBu + so + d0, Bg + kb);
            CP16(sBu + so + d1, Bg + kb + 32);
        }
        CP_COMMIT();
    }

    #pragma unroll
    for (int nf = 0; nf < 4; nf++) {
        const int cb = n0 + wn * 32 + nf * 8 + tq * 2;
        const int r0 = m0 + wm * 16 + gq;
        float2 bsv = *(const float2*)(d_bsum + cb);
        float2 v0 = make_float2(acc[nf][0] + bsv.x, acc[nf][1] + bsv.y);
        float2 v1 = make_float2(acc[nf][2] + bsv.x, acc[nf][3] + bsv.y);
        *(float2*)(d_xproj + (size_t)r0 * G4 + cb)       = v0;
        *(float2*)(d_xproj + (size_t)(r0 + 8) * G4 + cb) = v1;
    }
}

// ---------------- grid barrier (128 CTAs co-resident) ----------------
__device__ __forceinline__ void grid_barrier(unsigned target)
{
    __syncthreads();
    if (threadIdx.x == 0) {
        __threadfence();
        atomicAdd(&d_bar, 1u);
        volatile unsigned* p = &d_bar;
        while (*p < target) { }
        __threadfence();
    }
    __syncthreads();
}

// ---------------- phase 2: persistent recurrent kernel ----------------
__global__ __launch_bounds__(PTHREADS, 1) void lstm_persistent_c0(
    float* __restrict__ out, const float* __restrict__ c0)
{
    extern __shared__ __align__(1024) char smem_raw[];
    const uint32_t sbase = smem_u32(smem_raw);
    float* gsum = (float*)(smem_raw + OFF_GSUM);

    const int cta  = blockIdx.x;
    const int tid  = threadIdx.x;
    const int lane = tid & 31;
    const int g    = tid >> 8;              // K-half group (0,1)
    const int gtid = tid & 255;
    const int gwid = gtid >> 5;             // warp in group 0..7
    const int wm = gwid & 1;                // m half (batch 32)
    const int wn = (gwid >> 1) & 1;         // n half (gate 32)
    const int wk = gwid >> 2;               // k quarter within group
    const int gq = lane >> 2, tq = lane & 3;
    const int n0 = cta * 64;                // permuted gate-row base
    const int KOFF = g * (HDIM / 2);
    const int NIT  = (HDIM / 2) / KT;       // 16

    const uint32_t aGrp = sbase + (uint32_t)g * 4 * ASTG;
    const uint32_t bGrp = sbase + OFF_SB + (uint32_t)g * 4 * ASTG;

    const int lrow = gtid >> 2, lch = gtid & 3;
    const int fp_s = fperm(lrow);
    const uint32_t d0 = (uint32_t)(lrow * 128 + ((lch ^ fp_s) << 4));
    const uint32_t d1 = (uint32_t)(lrow * 128 + (((lch + 4) ^ fp_s) << 4));
    const int scol = lch * 8;
    const __half* Bg = d_whh16 + (size_t)(n0 + lrow) * HDIM + KOFF + scol;

    const int fp_l = fperm(lane & 7);
    const uint32_t rowA0 = (uint32_t)((wm * 32 + (lane & 15)) * 128);
    const uint32_t rowA1 = rowA0 + 16 * 128;
    const uint32_t rowB0 = (uint32_t)((wn * 32 + ((lane >> 4) & 1) * 8 + (lane & 7)) * 128);
    const uint32_t rowB1 = rowB0 + 16 * 128;
    const int khA = (lane >> 4) & 1;
    const int khB = (lane >> 3) & 1;
    const int kb16 = wk * 2;

    const size_t HOFF = (size_t)T_STEPS * BATCH * HDIM;
    const size_t COFF = HOFF + (size_t)BATCH * HDIM;

    const int b1 = tid >> 4,        jj1 = tid & 15;
    const int b2 = 32 + (tid >> 4), jj2 = jj1;
    float creg1 = c0[b1 * HDIM + cta * 16 + jj1];
    float creg2 = c0[b2 * HDIM + cta * 16 + jj2];

    unsigned bar_target = 0;

#define ISSUE(SLOT, KB, HB) do {                                              \
        const __half* asrc_ = (HB) + (size_t)lrow * HDIM + KOFF + (KB) + scol;\
        const __half* bsrc_ = Bg + (KB);                                      \
        const uint32_t ao_ = aGrp + (uint32_t)(SLOT) * ASTG;                  \
        const uint32_t bo_ = bGrp + (uint32_t)(SLOT) * ASTG;                  \
        CP16(ao_ + d0, asrc_);                                                \
        CP16(ao_ + d1, asrc_ + 32);                                           \
        CP16(bo_ + d0, bsrc_);                                                \
        CP16(bo_ + d1, bsrc_ + 32);                                           \
        CP_COMMIT();                                                          \
    } while (0)

    {
        const __half* hbuf = d_h16[0];
        ISSUE(0, 0 * KT, hbuf);
        ISSUE(1, 1 * KT, hbuf);
        ISSUE(2, 2 * KT, hbuf);
    }

    #pragma unroll 1
    for (int t = 0; t < T_STEPS; ++t) {
        const __half* hbuf = d_h16[t & 1];
        float acc[2][4][4];
        #pragma unroll
        for (int i = 0; i < 2; i++)
            #pragma unroll
            for (int j = 0; j < 4; j++)
                #pragma unroll
                for (int q = 0; q < 4; q++) acc[i][j][q] = 0.0f;

        #pragma unroll 4
        for (int it = 0; it < NIT; ++it) {
            CP_WAIT2();
            asm volatile("bar.sync %0, 256;\n" :: "r"(g + 1) : "memory");
            const uint32_t At = aGrp + (uint32_t)(it & 3) * ASTG;
            const uint32_t Bt = bGrp + (uint32_t)(it & 3) * ASTG;
            #pragma unroll
            for (int kc = 0; kc < 2; ++kc) {
                const uint32_t ccA = (uint32_t)((((kb16 + kc) << 1) | khA) ^ fp_l) << 4;
                const uint32_t ccB = (uint32_t)((((kb16 + kc) << 1) | khB) ^ fp_l) << 4;
                uint32_t a0[4], a1[4], bb0[4], bb1[4];
                LDSM4(a0[0], a0[1], a0[2], a0[3], At + rowA0 + ccA);
                LDSM4(a1[0], a1[1], a1[2], a1[3], At + rowA1 + ccA);
                LDSM4(bb0[0], bb0[1], bb0[2], bb0[3], Bt + rowB0 + ccB);
                LDSM4(bb1[0], bb1[1], bb1[2], bb1[3], Bt + rowB1 + ccB);
                mma16816(acc[0][0], a0[0], a0[1], a0[2], a0[3], bb0[0], bb0[1]);
                mma16816(acc[0][1], a0[0], a0[1], a0[2], a0[3], bb0[2], bb0[3]);
                mma16816(acc[0][2], a0[0], a0[1], a0[2], a0[3], bb1[0], bb1[1]);
                mma16816(acc[0][3], a0[0], a0[1], a0[2], a0[3], bb1[2], bb1[3]);
                mma16816(acc[1][0], a1[0], a1[1], a1[2], a1[3], bb0[0], bb0[1]);
                mma16816(acc[1][1], a1[0], a1[1], a1[2], a1[3], bb0[2], bb0[3]);
                mma16816(acc[1][2], a1[0], a1[1], a1[2], a1[3], bb1[0], bb1[1]);
                mma16816(acc[1][3], a1[0], a1[1], a1[2], a1[3], bb1[2], bb1[3]);
            }
            const int nxt = it + 3;
            if (nxt < NIT) {
                ISSUE(nxt & 3, nxt * KT, hbuf);
            } else {
                CP_COMMIT();
            }
        }

        // epilogue: write this warp's partial slab (slab = g*2 + wk)
        {
            float* gs = gsum + (size_t)(g * 2 + wk) * GSLAB;
            #pragma unroll
            for (int mf = 0; mf < 2; ++mf) {
                const int row = wm * 32 + mf * 16 + gq;
                #pragma unroll
                for (int nf = 0; nf < 4; ++nf) {
                    const int col = wn * 32 + nf * 8 + tq * 2;
                    *(float2*)&gs[row * GSTR + col] =
                        make_float2(acc[mf][nf][0], acc[mf][nf][1]);
                    *(float2*)&gs[(row + 8) * GSTR + col] =
                        make_float2(acc[mf][nf][2], acc[mf][nf][3]);
                }
            }
        }
        __syncthreads();

        // pointwise LSTM + exp + partial softmax sum (MUFU-lean)
        __half* hN = d_h16[(t + 1) & 1];
        const float* xp = d_xproj + (size_t)t * BATCH * G4 + n0;
        float e1, e2;
        {
            const float* gb = gsum + (size_t)b1 * GSTR;
            const float* xr = xp + (size_t)b1 * G4;
            float ip = gb[jj1] + gb[GSLAB + jj1] + gb[2*GSLAB + jj1] + gb[3*GSLAB + jj1] + xr[jj1];
            float fpv= gb[16+jj1] + gb[GSLAB+16+jj1] + gb[2*GSLAB+16+jj1] + gb[3*GSLAB+16+jj1] + xr[16+jj1];
            float gp = gb[32+jj1] + gb[GSLAB+32+jj1] + gb[2*GSLAB+32+jj1] + gb[3*GSLAB+32+jj1] + xr[32+jj1];
            float op = gb[48+jj1] + gb[GSLAB+48+jj1] + gb[2*GSLAB+48+jj1] + gb[3*GSLAB+48+jj1] + xr[48+jj1];
            float ii = sigmoid_hw(ip), ff = sigmoid_hw(fpv);
            float gg = tanh_hw(gp),    oo = sigmoid_hw(op);
            float cn = ff * creg1 + ii * gg;
            creg1 = cn;
            float hn = oo * tanh_hw(cn);
            hN[b1 * HDIM + cta * 16 + jj1] = __float2half(hn);
            if (t == T_STEPS - 1) {
                out[HOFF + (size_t)b1 * HDIM + cta * 16 + jj1] = hn;
                out[COFF + (size_t)b1 * HDIM + cta * 16 + jj1] = cn;
            }
            e1 = exp_hw(hn);
        }
        {
            const float* gb = gsum + (size_t)b2 * GSTR;
            const float* xr = xp + (size_t)b2 * G4;
            float ip = gb[jj2] + gb[GSLAB + jj2] + gb[2*GSLAB + jj2] + gb[3*GSLAB + jj2] + xr[jj2];
            float fpv= gb[16+jj2] + gb[GSLAB+16+jj2] + gb[2*GSLAB+16+jj2] + gb[3*GSLAB+16+jj2] + xr[16+jj2];
            float gp = gb[32+jj2] + gb[GSLAB+32+jj2] + gb[2*GSLAB+32+jj2] + gb[3*GSLAB+32+jj2] + xr[32+jj2];
            float op = gb[48+jj2] + gb[GSLAB+48+jj2] + gb[2*GSLAB+48+jj2] + gb[3*GSLAB+48+jj2] + xr[48+jj2];
            float ii = sigmoid_hw(ip), ff = sigmoid_hw(fpv);
            float gg = tanh_hw(gp),    oo = sigmoid_hw(op);
            float cn = ff * creg2 + ii * gg;
            creg2 = cn;
            float hn = oo * tanh_hw(cn);
            hN[b2 * HDIM + cta * 16 + jj2] = __float2half(hn);
            if (t == T_STEPS - 1) {
                out[HOFF + (size_t)b2 * HDIM + cta * 16 + jj2] = hn;
                out[COFF + (size_t)b2 * HDIM + cta * 16 + jj2] = cn;
            }
            e2 = exp_hw(hn);
        }
        float v1 = e1, v2 = e2;
        #pragma unroll
        for (int o = 8; o > 0; o >>= 1) {
            v1 += __shfl_xor_sync(0xffffffffu, v1, o);
            v2 += __shfl_xor_sync(0xffffffffu, v2, o);
        }
        if ((lane & 15) == 0) {
            atomicAdd(&d_sum[t * BATCH + b1], v1);
            atomicAdd(&d_sum[t * BATCH + b2], v2);
        }

        bar_target += NCTAS;
        grid_barrier(bar_target);

        if (t + 1 < T_STEPS) {
            const __half* hnext = d_h16[(t + 1) & 1];
            ISSUE(0, 0 * KT, hnext);
            ISSUE(1, 1 * KT, hnext);
            ISSUE(2, 2 * KT, hnext);
        }
        {
            float s1 = __ldcg(&d_sum[t * BATCH + b1]);
            float s2 = __ldcg(&d_sum[t * BATCH + b2]);
            out[(size_t)t * BATCH * HDIM + (size_t)b1 * HDIM + cta * 16 + jj1] = e1 * (1.0f / s1);
            out[(size_t)t * BATCH * HDIM + (size_t)b2 * HDIM + cta * 16 + jj2] = e2 * (1.0f / s2);
        }
    }
#undef ISSUE
}

// ---------------- entry ----------------
extern "C" void kernel_launch(void* const* d_in, const int* in_sizes, int n_in,
                              void* d_out, int out_size)
{
    (void)in_sizes; (void)n_in; (void)out_size;
    const float* input = (const float*)d_in[0];
    const float* h0    = (const float*)d_in[1];
    const float* c0    = (const float*)d_in[2];
    const float* wih   = (const float*)d_in[3];
    const float* whh   = (const float*)d_in[4];
    const float* bih   = (const float*)d_in[5];
    const float* bhh   = (const float*)d_in[6];

    const int xsmem = 2 * STAGES * TILEHALFS * (int)sizeof(__half);
    cudaFuncSetAttribute(xproj_kernel,
                         cudaFuncAttributeMaxDynamicSharedMemorySize, xsmem);
    cudaFuncSetAttribute(lstm_persistent_c0,
                         cudaFuncAttributeMaxDynamicSharedMemorySize, PSMEM);

    prep_kernel<<<1024, 256>>>(input, h0, c0, wih, whh, bih, bhh);
    xproj_kernel<<<dim3(G4 / 64, (T_STEPS * BATCH) / 64), XTHREADS, xsmem>>>();
    lstm_persistent_c0<<<NCTAS, PTHREADS, PSMEM>>>((float*)d_out, c0);
}

// round 8
// speedup vs baseline: 2.5348x; 1.0975x over previous
#include <cuda_runtime.h>
#include <cuda_fp16.h>
#include <cstdint>

#define T_STEPS 256
#define BATCH   64
#define XDIM    512
#define HDIM    2048
#define G4      8192
#define NCTAS   128
#define PTHREADS 512
#define XTHREADS 256
#define KT      64                 // K-tile per stage (halfs) = 128 B rows
#define TILEHALFS (64*KT)
#define STAGES  4                  // xproj stages
#define PSTAGES 6                  // persistent-kernel stages
#define ASTG    8192               // stage tile bytes (64 rows * 128 B)
#define GSTR    68                 // gsum row stride (halfs)
#define GSLAB   (64*GSTR)          // halfs per slab

// persistent smem layout (bytes)
#define OFF_SB   (2*PSTAGES*ASTG)            // 98304  (A: 2 groups * 6 stages)
#define OFF_GSUM (OFF_SB + 2*PSTAGES*ASTG)   // 196608 (B same size)
#define PSMEM    (OFF_GSUM + 4*GSLAB*2)      // + 4 fp16 slabs = 231424 B

// ---------------- device scratch ----------------
__device__ __align__(16) __half d_in16 [T_STEPS * BATCH * XDIM];
__device__ __align__(16) __half d_wih16[G4 * XDIM];
__device__ __align__(16) __half d_whh16[G4 * HDIM];
__device__ __align__(16) float  d_bsum [G4];
__device__ __align__(16) float  d_xproj[(size_t)T_STEPS * BATCH * G4];
__device__ __align__(16) __half d_h16  [2][BATCH * HDIM];
__device__ __align__(16) float  d_sum  [T_STEPS * BATCH];
__device__ unsigned d_bar;

// ---------------- helpers ----------------
__device__ __forceinline__ void mma16816(float* c,
    uint32_t a0, uint32_t a1, uint32_t a2, uint32_t a3,
    uint32_t b0, uint32_t b1)
{
    asm volatile(
        "mma.sync.aligned.m16n8k16.row.col.f32.f16.f16.f32 "
        "{%0,%1,%2,%3},{%4,%5,%6,%7},{%8,%9},{%0,%1,%2,%3};\n"
        : "+f"(c[0]), "+f"(c[1]), "+f"(c[2]), "+f"(c[3])
        : "r"(a0), "r"(a1), "r"(a2), "r"(a3), "r"(b0), "r"(b1));
}
#define LDSM4(r0, r1, r2, r3, addr) \
    asm volatile("ldmatrix.sync.aligned.m8n8.x4.shared.b16 {%0,%1,%2,%3}, [%4];" \
        : "=r"(r0), "=r"(r1), "=r"(r2), "=r"(r3) : "r"(addr))

__device__ __forceinline__ float tanh_hw(float x) {
    float y;
    asm("tanh.approx.f32 %0, %1;" : "=f"(y) : "f"(x));
    return y;
}
__device__ __forceinline__ float sigmoid_hw(float x) {
    return fmaf(tanh_hw(0.5f * x), 0.5f, 0.5f);
}
__device__ __forceinline__ float exp_hw(float x) {
    float y;
    asm("ex2.approx.ftz.f32 %0, %1;" : "=f"(y) : "f"(x * 1.4426950408889634f));
    return y;
}

__device__ __forceinline__ uint32_t smem_u32(const void* p) {
    return (uint32_t)__cvta_generic_to_shared(p);
}
__device__ __forceinline__ int fperm(int r) { return ((r & 1) << 2) | ((r & 7) >> 1); }

#define CP16(dst_u32, src_ptr) \
    asm volatile("cp.async.cg.shared.global [%0], [%1], 16;\n" :: "r"(dst_u32), "l"(src_ptr))
#define CP_COMMIT() asm volatile("cp.async.commit_group;\n" ::: "memory")
#define CP_WAIT2()  asm volatile("cp.async.wait_group 2;\n" ::: "memory")
#define CP_WAIT4()  asm volatile("cp.async.wait_group 4;\n" ::: "memory")

// row permutation: dst row (CTA-major: cta*64 + gate*16 + jj) -> src gate row
__device__ __forceinline__ int perm_src_row(int r) {
    int cta = r >> 6;
    int ln  = r & 63;
    int gate = ln >> 4;
    int jj   = ln & 15;
    return gate * HDIM + cta * 16 + jj;
}

// ---------------- phase 0 ----------------
__global__ __launch_bounds__(256) void prep_kernel(
    const float* __restrict__ input, const float* __restrict__ h0,
    const float* __restrict__ c0,    const float* __restrict__ wih,
    const float* __restrict__ whh,   const float* __restrict__ bih,
    const float* __restrict__ bhh)
{
    (void)c0;
    const int i0 = blockIdx.x * blockDim.x + threadIdx.x;
    const int stride = gridDim.x * blockDim.x;
    if (i0 == 0) d_bar = 0u;
    for (int i = i0; i < T_STEPS * BATCH * XDIM; i += stride)
        d_in16[i] = __float2half(input[i]);
    for (int i = i0; i < G4 * XDIM; i += stride) {
        int r = i >> 9, k = i & (XDIM - 1);
        d_wih16[i] = __float2half(wih[perm_src_row(r) * XDIM + k]);
    }
    for (int i = i0; i < G4 * HDIM; i += stride) {
        int r = i >> 11, k = i & (HDIM - 1);
        d_whh16[i] = __float2half(whh[(size_t)perm_src_row(r) * HDIM + k]);
    }
    for (int i = i0; i < G4; i += stride) {
        int s = perm_src_row(i);
        d_bsum[i] = bih[s] + bhh[s];
    }
    for (int i = i0; i < BATCH * HDIM; i += stride)
        d_h16[0][i] = __float2half(h0[i]);
    for (int i = i0; i < T_STEPS * BATCH; i += stride)
        d_sum[i] = 0.0f;
}

// ---------------- phase 1: xproj (unchanged from R6/R7) ----------------
__global__ __launch_bounds__(XTHREADS) void xproj_kernel()
{
    extern __shared__ __align__(16) char xsmem_raw[];
    __half* sAll = (__half*)xsmem_raw;
    __half* sA = sAll;
    __half* sB = sAll + STAGES * TILEHALFS;

    const int tid  = threadIdx.x;
    const int lane = tid & 31, wid = tid >> 5;
    const int wm = wid >> 1, wn = wid & 1;
    const int gq = lane >> 2, tq = lane & 3;
    const int fp = fperm(gq);
    const int n0 = blockIdx.x * 64;
    const int m0 = blockIdx.y * 64;

    const int lrow = tid >> 2, lch = tid & 3;
    const int fp_s = fperm(lrow);
    const uint32_t sAu = smem_u32(sA), sBu = smem_u32(sB);
    const uint32_t d0 = (uint32_t)(lrow * KT + ((lch ^ fp_s) * 8)) * 2;
    const uint32_t d1 = (uint32_t)(lrow * KT + (((lch + 4) ^ fp_s) * 8)) * 2;
    const int scol = lch * 8;

    const __half* Ag = d_in16  + (size_t)(m0 + lrow) * XDIM + scol;
    const __half* Bg = d_wih16 + (size_t)(n0 + lrow) * XDIM + scol;

    float acc[4][4];
    #pragma unroll
    for (int i = 0; i < 4; i++)
        #pragma unroll
        for (int j = 0; j < 4; j++) acc[i][j] = 0.0f;

    const int NITX = XDIM / KT;
    #pragma unroll
    for (int st = 0; st < 3; ++st) {
        const int kb = st * KT;
        CP16(sAu + (uint32_t)st * TILEHALFS * 2 + d0, Ag + kb);
        CP16(sAu + (uint32_t)st * TILEHALFS * 2 + d1, Ag + kb + 32);
        CP16(sBu + (uint32_t)st * TILEHALFS * 2 + d0, Bg + kb);
        CP16(sBu + (uint32_t)st * TILEHALFS * 2 + d1, Bg + kb + 32);
        CP_COMMIT();
    }

    const int rowA = wm * 16 + gq;
    #pragma unroll 1
    for (int it = 0; it < NITX; ++it) {
        CP_WAIT2();
        __syncthreads();
        const __half* At = sA + (it & 3) * TILEHALFS;
        const __half* Bt = sB + (it & 3) * TILEHALFS;
        #pragma unroll
        for (int k = 0; k < 4; ++k) {
            const int c0o = ((2 * k) ^ fp) * 8 + tq * 2;
            const int c1o = ((2 * k + 1) ^ fp) * 8 + tq * 2;
            uint32_t a0 = *(const uint32_t*)(At + rowA * KT + c0o);
            uint32_t a1 = *(const uint32_t*)(At + (rowA + 8) * KT + c0o);
            uint32_t a2 = *(const uint32_t*)(At + rowA * KT + c1o);
            uint32_t a3 = *(const uint32_t*)(At + (rowA + 8) * KT + c1o);
            #pragma unroll
            for (int nf = 0; nf < 4; nf++) {
                const int rowB = wn * 32 + nf * 8 + gq;
                uint32_t b0 = *(const uint32_t*)(Bt + rowB * KT + c0o);
                uint32_t b1 = *(const uint32_t*)(Bt + rowB * KT + c1o);
                mma16816(acc[nf], a0, a1, a2, a3, b0, b1);
            }
        }
        __syncthreads();
        const int nxt = it + 3;
        if (nxt < NITX) {
            const uint32_t so = (uint32_t)(nxt & 3) * TILEHALFS * 2;
            const int kb = nxt * KT;
            CP16(sAu + so + d0, Ag + kb);
            CP16(sAu + so + d1, Ag + kb + 32);
            CP16(sBu + so + d0, Bg + kb);
            CP16(sBu + so + d1, Bg + kb + 32);
        }
        CP_COMMIT();
    }

    #pragma unroll
    for (int nf = 0; nf < 4; nf++) {
        const int cb = n0 + wn * 32 + nf * 8 + tq * 2;
        const int r0 = m0 + wm * 16 + gq;
        float2 bsv = *(const float2*)(d_bsum + cb);
        float2 v0 = make_float2(acc[nf][0] + bsv.x, acc[nf][1] + bsv.y);
        float2 v1 = make_float2(acc[nf][2] + bsv.x, acc[nf][3] + bsv.y);
        *(float2*)(d_xproj + (size_t)r0 * G4 + cb)       = v0;
        *(float2*)(d_xproj + (size_t)(r0 + 8) * G4 + cb) = v1;
    }
}

// ---------------- grid barrier (128 CTAs co-resident) ----------------
__device__ __forceinline__ void grid_barrier(unsigned target)
{
    __syncthreads();
    if (threadIdx.x == 0) {
        __threadfence();
        atomicAdd(&d_bar, 1u);
        volatile unsigned* p = &d_bar;
        while (*p < target) { }
        __threadfence();
    }
    __syncthreads();
}

// ---------------- phase 2: persistent recurrent kernel ----------------
__global__ __launch_bounds__(PTHREADS, 1) void lstm_persistent_c0(
    float* __restrict__ out, const float* __restrict__ c0)
{
    extern __shared__ __align__(1024) char smem_raw[];
    const uint32_t sbase = smem_u32(smem_raw);
    __half* gsum = (__half*)(smem_raw + OFF_GSUM);

    const int cta  = blockIdx.x;
    const int tid  = threadIdx.x;
    const int lane = tid & 31;
    const int g    = tid >> 8;              // K-half group (0,1)
    const int gtid = tid & 255;
    const int gwid = gtid >> 5;             // warp in group 0..7
    const int wm = gwid & 1;                // m half (batch 32)
    const int wn = (gwid >> 1) & 1;         // n half (gate 32)
    const int wk = gwid >> 2;               // k quarter within group
    const int gq = lane >> 2, tq = lane & 3;
    const int n0 = cta * 64;                // permuted gate-row base
    const int KOFF = g * (HDIM / 2);
    const int NIT  = (HDIM / 2) / KT;       // 16

    const uint32_t aGrp = sbase + (uint32_t)g * PSTAGES * ASTG;
    const uint32_t bGrp = sbase + OFF_SB + (uint32_t)g * PSTAGES * ASTG;

    const int lrow = gtid >> 2, lch = gtid & 3;
    const int fp_s = fperm(lrow);
    const uint32_t d0 = (uint32_t)(lrow * 128 + ((lch ^ fp_s) << 4));
    const uint32_t d1 = (uint32_t)(lrow * 128 + (((lch + 4) ^ fp_s) << 4));
    const int scol = lch * 8;
    const __half* Bg = d_whh16 + (size_t)(n0 + lrow) * HDIM + KOFF + scol;

    const int fp_l = fperm(lane & 7);
    const uint32_t rowA0 = (uint32_t)((wm * 32 + (lane & 15)) * 128);
    const uint32_t rowA1 = rowA0 + 16 * 128;
    const uint32_t rowB0 = (uint32_t)((wn * 32 + ((lane >> 4) & 1) * 8 + (lane & 7)) * 128);
    const uint32_t rowB1 = rowB0 + 16 * 128;
    const int khA = (lane >> 4) & 1;
    const int khB = (lane >> 3) & 1;
    const int kb16 = wk * 2;

    const size_t HOFF = (size_t)T_STEPS * BATCH * HDIM;
    const size_t COFF = HOFF + (size_t)BATCH * HDIM;

    const int b1 = tid >> 4,        jj1 = tid & 15;
    const int b2 = 32 + (tid >> 4), jj2 = jj1;
    float creg1 = c0[b1 * HDIM + cta * 16 + jj1];
    float creg2 = c0[b2 * HDIM + cta * 16 + jj2];

    unsigned bar_target = 0;

#define ISSUE(SLOT, KB, HB) do {                                              \
        const __half* asrc_ = (HB) + (size_t)lrow * HDIM + KOFF + (KB) + scol;\
        const __half* bsrc_ = Bg + (KB);                                      \
        const uint32_t ao_ = aGrp + (uint32_t)(SLOT) * ASTG;                  \
        const uint32_t bo_ = bGrp + (uint32_t)(SLOT) * ASTG;                  \
        CP16(ao_ + d0, asrc_);                                                \
        CP16(ao_ + d1, asrc_ + 32);                                           \
        CP16(bo_ + d0, bsrc_);                                                \
        CP16(bo_ + d1, bsrc_ + 32);                                           \
        CP_COMMIT();                                                          \
    } while (0)

    // initial prologue: 5 stages of step 0
    {
        const __half* hbuf = d_h16[0];
        #pragma unroll
        for (int st = 0; st < 5; ++st) ISSUE(st, st * KT, hbuf);
    }

    #pragma unroll 1
    for (int t = 0; t < T_STEPS; ++t) {
        const __half* hbuf = d_h16[t & 1];

        // prefetch this step's xproj gate values (hidden behind GEMM)
        const float* xp = d_xproj + (size_t)t * BATCH * G4 + n0;
        const float* xr1 = xp + (size_t)b1 * G4;
        const float* xr2 = xp + (size_t)b2 * G4;
        float xv1[4], xv2[4];
        #pragma unroll
        for (int q = 0; q < 4; ++q) {
            xv1[q] = xr1[q * 16 + jj1];
            xv2[q] = xr2[q * 16 + jj2];
        }

        float acc[2][4][4];
        #pragma unroll
        for (int i = 0; i < 2; i++)
            #pragma unroll
            for (int j = 0; j < 4; j++)
                #pragma unroll
                for (int q = 0; q < 4; q++) acc[i][j][q] = 0.0f;

        #pragma unroll 4
        for (int it = 0; it < NIT; ++it) {
            CP_WAIT4();
            asm volatile("bar.sync %0, 256;\n" :: "r"(g + 1) : "memory");
            const int slot = it % PSTAGES;
            const uint32_t At = aGrp + (uint32_t)slot * ASTG;
            const uint32_t Bt = bGrp + (uint32_t)slot * ASTG;
            #pragma unroll
            for (int kc = 0; kc < 2; ++kc) {
                const uint32_t ccA = (uint32_t)((((kb16 + kc) << 1) | khA) ^ fp_l) << 4;
                const uint32_t ccB = (uint32_t)((((kb16 + kc) << 1) | khB) ^ fp_l) << 4;
                uint32_t a0[4], a1[4], bb0[4], bb1[4];
                LDSM4(a0[0], a0[1], a0[2], a0[3], At + rowA0 + ccA);
                LDSM4(a1[0], a1[1], a1[2], a1[3], At + rowA1 + ccA);
                LDSM4(bb0[0], bb0[1], bb0[2], bb0[3], Bt + rowB0 + ccB);
                LDSM4(bb1[0], bb1[1], bb1[2], bb1[3], Bt + rowB1 + ccB);
                mma16816(acc[0][0], a0[0], a0[1], a0[2], a0[3], bb0[0], bb0[1]);
                mma16816(acc[0][1], a0[0], a0[1], a0[2], a0[3], bb0[2], bb0[3]);
                mma16816(acc[0][2], a0[0], a0[1], a0[2], a0[3], bb1[0], bb1[1]);
                mma16816(acc[0][3], a0[0], a0[1], a0[2], a0[3], bb1[2], bb1[3]);
                mma16816(acc[1][0], a1[0], a1[1], a1[2], a1[3], bb0[0], bb0[1]);
                mma16816(acc[1][1], a1[0], a1[1], a1[2], a1[3], bb0[2], bb0[3]);
                mma16816(acc[1][2], a1[0], a1[1], a1[2], a1[3], bb1[0], bb1[1]);
                mma16816(acc[1][3], a1[0], a1[1], a1[2], a1[3], bb1[2], bb1[3]);
            }
            const int nxt = it + 5;
            if (nxt < NIT) {
                ISSUE(nxt % PSTAGES, nxt * KT, hbuf);
            } else {
                CP_COMMIT();
            }
        }

        // epilogue: write this warp's partial slab in fp16 (slab = g*2 + wk)
        {
            __half* gs = gsum + (size_t)(g * 2 + wk) * GSLAB;
            #pragma unroll
            for (int mf = 0; mf < 2; ++mf) {
                const int row = wm * 32 + mf * 16 + gq;
                #pragma unroll
                for (int nf = 0; nf < 4; ++nf) {
                    const int col = wn * 32 + nf * 8 + tq * 2;
                    *(__half2*)&gs[row * GSTR + col] =
                        __floats2half2_rn(acc[mf][nf][0], acc[mf][nf][1]);
                    *(__half2*)&gs[(row + 8) * GSTR + col] =
                        __floats2half2_rn(acc[mf][nf][2], acc[mf][nf][3]);
                }
            }
        }
        __syncthreads();

        // pointwise LSTM + exp + partial softmax sum
        __half* hN = d_h16[(t + 1) & 1];
        float e1, e2;
        {
            const __half* gb = gsum + (size_t)b1 * GSTR;
            float ip = __half2float(gb[jj1]) + __half2float(gb[GSLAB + jj1])
                     + __half2float(gb[2*GSLAB + jj1]) + __half2float(gb[3*GSLAB + jj1]) + xv1[0];
            float fpv= __half2float(gb[16+jj1]) + __half2float(gb[GSLAB+16+jj1])
                     + __half2float(gb[2*GSLAB+16+jj1]) + __half2float(gb[3*GSLAB+16+jj1]) + xv1[1];
            float gp = __half2float(gb[32+jj1]) + __half2float(gb[GSLAB+32+jj1])
                     + __half2float(gb[2*GSLAB+32+jj1]) + __half2float(gb[3*GSLAB+32+jj1]) + xv1[2];
            float op = __half2float(gb[48+jj1]) + __half2float(gb[GSLAB+48+jj1])
                     + __half2float(gb[2*GSLAB+48+jj1]) + __half2float(gb[3*GSLAB+48+jj1]) + xv1[3];
            float ii = sigmoid_hw(ip), ff = sigmoid_hw(fpv);
            float gg = tanh_hw(gp),    oo = sigmoid_hw(op);
            float cn = ff * creg1 + ii * gg;
            creg1 = cn;
            float hn = oo * tanh_hw(cn);
            hN[b1 * HDIM + cta * 16 + jj1] = __float2half(hn);
            if (t == T_STEPS - 1) {
                out[HOFF + (size_t)b1 * HDIM + cta * 16 + jj1] = hn;
                out[COFF + (size_t)b1 * HDIM + cta * 16 + jj1] = cn;
            }
            e1 = exp_hw(hn);
        }
        {
            const __half* gb = gsum + (size_t)b2 * GSTR;
            float ip = __half2float(gb[jj2]) + __half2float(gb[GSLAB + jj2])
                     + __half2float(gb[2*GSLAB + jj2]) + __half2float(gb[3*GSLAB + jj2]) + xv2[0];
            float fpv= __half2float(gb[16+jj2]) + __half2float(gb[GSLAB+16+jj2])
                     + __half2float(gb[2*GSLAB+16+jj2]) + __half2float(gb[3*GSLAB+16+jj2]) + xv2[1];
            float gp = __half2float(gb[32+jj2]) + __half2float(gb[GSLAB+32+jj2])
                     + __half2float(gb[2*GSLAB+32+jj2]) + __half2float(gb[3*GSLAB+32+jj2]) + xv2[2];
            float op = __half2float(gb[48+jj2]) + __half2float(gb[GSLAB+48+jj2])
                     + __half2float(gb[2*GSLAB+48+jj2]) + __half2float(gb[3*GSLAB+48+jj2]) + xv2[3];
            float ii = sigmoid_hw(ip), ff = sigmoid_hw(fpv);
            float gg = tanh_hw(gp),    oo = sigmoid_hw(op);
            float cn = ff * creg2 + ii * gg;
            creg2 = cn;
            float hn = oo * tanh_hw(cn);
            hN[b2 * HDIM + cta * 16 + jj2] = __float2half(hn);
            if (t == T_STEPS - 1) {
                out[HOFF + (size_t)b2 * HDIM + cta * 16 + jj2] = hn;
                out[COFF + (size_t)b2 * HDIM + cta * 16 + jj2] = cn;
            }
            e2 = exp_hw(hn);
        }
        float v1 = e1, v2 = e2;
        #pragma unroll
        for (int o = 8; o > 0; o >>= 1) {
            v1 += __shfl_xor_sync(0xffffffffu, v1, o);
            v2 += __shfl_xor_sync(0xffffffffu, v2, o);
        }
        if ((lane & 15) == 0) {
            atomicAdd(&d_sum[t * BATCH + b1], v1);
            atomicAdd(&d_sum[t * BATCH + b2], v2);
        }

        bar_target += NCTAS;
        grid_barrier(bar_target);

        // next step's prologue first (hide refill), then normalize y
        if (t + 1 < T_STEPS) {
            const __half* hnext = d_h16[(t + 1) & 1];
            #pragma unroll
            for (int st = 0; st < 5; ++st) ISSUE(st, st * KT, hnext);
        }
        {
            float s1 = __ldcg(&d_sum[t * BATCH + b1]);
            float s2 = __ldcg(&d_sum[t * BATCH + b2]);
            out[(size_t)t * BATCH * HDIM + (size_t)b1 * HDIM + cta * 16 + jj1] = e1 * (1.0f / s1);
            out[(size_t)t * BATCH * HDIM + (size_t)b2 * HDIM + cta * 16 + jj2] = e2 * (1.0f / s2);
        }
    }
#undef ISSUE
}

// ---------------- entry ----------------
extern "C" void kernel_launch(void* const* d_in, const int* in_sizes, int n_in,
                              void* d_out, int out_size)
{
    (void)in_sizes; (void)n_in; (void)out_size;
    const float* input = (const float*)d_in[0];
    const float* h0    = (const float*)d_in[1];
    const float* c0    = (const float*)d_in[2];
    const float* wih   = (const float*)d_in[3];
    const float* whh   = (const float*)d_in[4];
    const float* bih   = (const float*)d_in[5];
    const float* bhh   = (const float*)d_in[6];

    const int xsmem = 2 * STAGES * TILEHALFS * (int)sizeof(__half);
    cudaFuncSetAttribute(xproj_kernel,
                         cudaFuncAttributeMaxDynamicSharedMemorySize, xsmem);
    cudaFuncSetAttribute(lstm_persistent_c0,
                         cudaFuncAttributeMaxDynamicSharedMemorySize, PSMEM);

    prep_kernel<<<1024, 256>>>(input, h0, c0, wih, whh, bih, bhh);
    xproj_kernel<<<dim3(G4 / 64, (T_STEPS * BATCH) / 64), XTHREADS, xsmem>>>();
    lstm_persistent_c0<<<NCTAS, PTHREADS, PSMEM>>>((float*)d_out, c0);
}